// round 5
// baseline (speedup 1.0000x reference)
#include <cuda_runtime.h>
#include <math.h>
#include <stdint.h>

// Problem constants
#define TT 2048
#define DD 1024
#define FF 2048
#define CC 4
#define EE 4
#define NEXP 16
#define EPSL 1e-5f

#define BM1 128
#define BN1 128
#define BKK 32
#define NST 3
#define APAD 36
#define BPAD 136
#define NTH 512

// ---------------- device scratch (static, no allocation) ----------------
__device__ float g_A[16ULL*2048ULL*1024ULL];   // LN'd gathered input rows (tf32-rounded)
__device__ float g_H[16ULL*2048ULL*2048ULL];   // activated hidden per expert slot
__device__ float g_Z[16ULL*2048ULL*1024ULL];   // expert output rows (pre-LN, + residual)
__device__ int   g_cnt[NEXP];
__device__ int   g_tok[NEXP*TT];
__device__ float g_mu[TT];
__device__ float g_rstd[TT];
__device__ int   g_sel[TT*2];
__device__ float g_gate[TT*2];
__device__ int   g_islot[TT*4];
__device__ int   g_ipos[TT*4];
__device__ float g_icoef[TT*4];

// ---------------- helpers ----------------
__device__ __forceinline__ float tf32r(float f) {
    uint32_t r;
    asm("cvt.rna.tf32.f32 %0, %1;" : "=r"(r) : "f"(f));
    return __uint_as_float(r);
}

__device__ __forceinline__ void mma_tf32(float* c, const uint32_t* a, const uint32_t* b) {
    asm volatile(
        "mma.sync.aligned.m16n8k8.row.col.f32.tf32.tf32.f32 "
        "{%0,%1,%2,%3}, {%4,%5,%6,%7}, {%8,%9}, {%0,%1,%2,%3};\n"
        : "+f"(c[0]), "+f"(c[1]), "+f"(c[2]), "+f"(c[3])
        : "r"(a[0]), "r"(a[1]), "r"(a[2]), "r"(a[3]), "r"(b[0]), "r"(b[1]));
}

__device__ __forceinline__ void cp16(uint32_t dst, const void* src) {
    asm volatile("cp.async.cg.shared.global [%0], [%1], 16;\n" :: "r"(dst), "l"(src));
}
__device__ __forceinline__ void cp_commit() {
    asm volatile("cp.async.commit_group;\n" ::: "memory");
}
__device__ __forceinline__ void cp_wait1() {
    asm volatile("cp.async.wait_group 1;\n" ::: "memory");
}

// block reduction for mean/var over DD elements, blockDim = 256
__device__ __forceinline__ void block_meanvar_256(float s, float s2, float* rbuf,
                                                  float& mu, float& rs)
{
    int tid = threadIdx.x, lane = tid & 31, w = tid >> 5;
    __syncthreads();
    #pragma unroll
    for (int o = 16; o; o >>= 1) {
        s  += __shfl_down_sync(0xffffffffu, s,  o);
        s2 += __shfl_down_sync(0xffffffffu, s2, o);
    }
    if (lane == 0) { rbuf[w] = s; rbuf[8 + w] = s2; }
    __syncthreads();
    if (tid == 0) {
        float S = 0.f, S2 = 0.f;
        #pragma unroll
        for (int ww = 0; ww < 8; ww++) { S += rbuf[ww]; S2 += rbuf[8 + ww]; }
        float m = S / (float)DD;
        rbuf[16] = m;
        rbuf[17] = rsqrtf(S2 / (float)DD - m * m + EPSL);
    }
    __syncthreads();
    mu = rbuf[16];
    rs = rbuf[17];
}

// ---------------- small kernels ----------------
__global__ void zero_cnt_kernel()
{
    if (threadIdx.x < NEXP) g_cnt[threadIdx.x] = 0;
}

__global__ void routing_kernel(const float* __restrict__ x,
                               const float* __restrict__ Wrc, const float* __restrict__ brc,
                               const float* __restrict__ Wre, const float* __restrict__ bre)
{
    int t = blockIdx.x;
    __shared__ float xs[DD];
    __shared__ float rbuf[16];
    __shared__ float lgs[20];
    int tid = threadIdx.x;          // 128 threads
    int lane = tid & 31, wid = tid >> 5;

    float s = 0.f, s2 = 0.f;
    for (int d = tid; d < DD; d += 128) {
        float v = x[(size_t)t * DD + d];
        xs[d] = v; s += v; s2 += v * v;
    }
    #pragma unroll
    for (int o = 16; o; o >>= 1) {
        s  += __shfl_down_sync(0xffffffffu, s,  o);
        s2 += __shfl_down_sync(0xffffffffu, s2, o);
    }
    if (lane == 0) { rbuf[wid] = s; rbuf[8 + wid] = s2; }
    __syncthreads();
    if (tid == 0) {
        float S  = rbuf[0] + rbuf[1] + rbuf[2] + rbuf[3];
        float S2 = rbuf[8] + rbuf[9] + rbuf[10] + rbuf[11];
        float mu = S / (float)DD;
        float var = S2 / (float)DD - mu * mu;
        g_mu[t] = mu;
        g_rstd[t] = rsqrtf(var + EPSL);
    }

    for (int v = wid; v < 20; v += 4) {
        float acc = 0.f;
        if (v < CC) {
            for (int d = lane; d < DD; d += 32) acc += xs[d] * Wrc[d * CC + v];
        } else {
            int cc = (v - 4) >> 2, e = (v - 4) & 3;
            const float* wp = Wre + (size_t)cc * DD * EE + e;
            for (int d = lane; d < DD; d += 32) acc += xs[d] * wp[d * EE];
        }
        #pragma unroll
        for (int o = 16; o; o >>= 1) acc += __shfl_down_sync(0xffffffffu, acc, o);
        if (lane == 0) lgs[v] = acc;
    }
    __syncthreads();

    if (tid == 0) {
        float p[CC];
        float mx = -1e30f;
        for (int c = 0; c < CC; c++) { p[c] = lgs[c] + brc[c]; mx = fmaxf(mx, p[c]); }
        float ss = 0.f;
        for (int c = 0; c < CC; c++) { p[c] = expf(p[c] - mx); ss += p[c]; }
        for (int c = 0; c < CC; c++) p[c] /= ss;
        int i0 = 0;
        for (int c = 1; c < CC; c++) if (p[c] > p[i0]) i0 = c;
        int i1 = -1;
        for (int c = 0; c < CC; c++) if (c != i0 && (i1 < 0 || p[c] > p[i1])) i1 = c;
        float swt = p[i0] + p[i1];
        int sel[2] = { i0, i1 };
        float gv[2] = { p[i0] / swt, p[i1] / swt };

        for (int sI = 0; sI < 2; sI++) {
            int cc = sel[sI];
            g_sel[t * 2 + sI]  = cc;
            g_gate[t * 2 + sI] = gv[sI];
            float el[EE];
            for (int e = 0; e < EE; e++) el[e] = lgs[4 + cc * 4 + e] + bre[cc * EE + e];
            int e0 = 0;
            for (int e = 1; e < EE; e++) if (el[e] > el[e0]) e0 = e;
            int e1 = -1;
            for (int e = 0; e < EE; e++) if (e != e0 && (e1 < 0 || el[e] > el[e1])) e1 = e;
            float z = expf(el[e1] - el[e0]);
            float w0 = 1.f / (1.f + z), w1 = z / (1.f + z);
            int   eS[2] = { e0, e1 };
            float wS[2] = { w0, w1 };
            for (int q = 0; q < 2; q++) {
                int slot = cc * EE + eS[q];
                int pos = atomicAdd(&g_cnt[slot], 1);
                g_tok[slot * TT + pos] = t;
                g_islot[t * 4 + sI * 2 + q] = slot;
                g_ipos [t * 4 + sI * 2 + q] = pos;
                g_icoef[t * 4 + sI * 2 + q] = wS[q];
            }
        }
    }
}

// gather + input LayerNorm + tf32 rounding -> g_A
__global__ void prep_kernel(const float* __restrict__ x,
                            const float* __restrict__ ling, const float* __restrict__ linb)
{
    int idx = blockIdx.y;
    int i = blockIdx.x;
    if (i >= g_cnt[idx]) return;
    int tok = g_tok[idx * TT + i];
    float mu = g_mu[tok], rs = g_rstd[tok];
    const float4* xr = (const float4*)(x + (size_t)tok * DD);
    const float4* gp = (const float4*)(ling + (size_t)idx * DD);
    const float4* bp = (const float4*)(linb + (size_t)idx * DD);
    float4* ar = (float4*)(g_A + ((size_t)idx * TT + i) * DD);
    int d = threadIdx.x;           // 256 threads, 1 float4 each
    float4 xv = xr[d], gv = gp[d], bv = bp[d];
    float4 o;
    o.x = tf32r((xv.x - mu) * rs * gv.x + bv.x);
    o.y = tf32r((xv.y - mu) * rs * gv.y + bv.y);
    o.z = tf32r((xv.z - mu) * rs * gv.z + bv.z);
    o.w = tf32r((xv.w - mu) * rs * gv.w + bv.w);
    ar[d] = o;
}

// GEMM1: H = act( A @ W1 [, @ W2] ).  128x128 block, 512 threads, 16 warps.
template<bool DUAL>
__global__ void __launch_bounds__(NTH, 1) gemm1_mma_kernel(
    const float* __restrict__ W1, const float* __restrict__ W2)
{
    int z = blockIdx.z;
    int idx = DUAL ? ((z >> 1) * 4 + ((z & 1) ? 3 : 0))
                   : ((z >> 1) * 4 + ((z & 1) ? 2 : 1));
    int Nt = g_cnt[idx];
    int m0 = blockIdx.y * BM1;
    if (m0 >= Nt) return;
    int n0 = blockIdx.x * BN1;
    int act = (idx & 3) % 3;
    const float* W1b = W1 + (size_t)idx * DD * FF;
    const float* W2b = W2 + (size_t)idx * DD * FF;
    const float* Ab  = g_A + (size_t)idx * TT * DD;

    extern __shared__ float smem[];
    float (*As)[BM1][APAD]  = (float (*)[BM1][APAD])smem;
    float (*B1s)[BKK][BPAD] = (float (*)[BKK][BPAD])(smem + NST * BM1 * APAD);
    float (*B2s)[BKK][BPAD] = (float (*)[BKK][BPAD])(smem + NST * BM1 * APAD + NST * BKK * BPAD);

    int tid = threadIdx.x;
    int lane = tid & 31;
    int g = lane >> 2, tig = lane & 3;
    int w = tid >> 5, wm = w & 3, wn = w >> 2;   // 16 warps: 4x4

    // cp.async indexing: A chunk 128x32 floats (2 cp/thread), B chunk 32x128 (2 cp/thread each)
    int arow = tid >> 3, acol = (tid & 7) << 2;     // rows 0..63 (+64)
    int brr  = tid >> 4, bcc  = (tid & 15) << 2;    // rows 0..31, cols 0..60 (+64)

    float acc1[2][4][4] = {};
    float acc2[DUAL ? 2 : 1][4][4] = {};

    auto issue = [&](int st, int k0) {
        cp16((uint32_t)__cvta_generic_to_shared(&As[st][arow][acol]),
             Ab + (size_t)(m0 + arow) * DD + k0 + acol);
        cp16((uint32_t)__cvta_generic_to_shared(&As[st][arow + 64][acol]),
             Ab + (size_t)(m0 + arow + 64) * DD + k0 + acol);
        cp16((uint32_t)__cvta_generic_to_shared(&B1s[st][brr][bcc]),
             W1b + (size_t)(k0 + brr) * FF + n0 + bcc);
        cp16((uint32_t)__cvta_generic_to_shared(&B1s[st][brr][bcc + 64]),
             W1b + (size_t)(k0 + brr) * FF + n0 + bcc + 64);
        if (DUAL) {
            cp16((uint32_t)__cvta_generic_to_shared(&B2s[st][brr][bcc]),
                 W2b + (size_t)(k0 + brr) * FF + n0 + bcc);
            cp16((uint32_t)__cvta_generic_to_shared(&B2s[st][brr][bcc + 64]),
                 W2b + (size_t)(k0 + brr) * FF + n0 + bcc + 64);
        }
    };

    const int NIT = DD / BKK;       // 32
    issue(0, 0);          cp_commit();
    issue(1, BKK);        cp_commit();

    for (int it = 0; it < NIT; ++it) {
        cp_wait1();
        __syncthreads();
        int buf = it % NST;
        #pragma unroll
        for (int s = 0; s < 4; ++s) {
            int kk = s * 8 + tig;
            uint32_t af[2][4];
            #pragma unroll
            for (int mi = 0; mi < 2; ++mi) {
                int r = wm * 32 + mi * 16 + g;
                af[mi][0] = __float_as_uint(As[buf][r    ][kk    ]);
                af[mi][1] = __float_as_uint(As[buf][r + 8][kk    ]);
                af[mi][2] = __float_as_uint(As[buf][r    ][kk + 4]);
                af[mi][3] = __float_as_uint(As[buf][r + 8][kk + 4]);
            }
            #pragma unroll
            for (int ni = 0; ni < 4; ++ni) {
                int n = wn * 32 + ni * 8 + g;
                uint32_t bf[2];
                bf[0] = __float_as_uint(B1s[buf][kk    ][n]);
                bf[1] = __float_as_uint(B1s[buf][kk + 4][n]);
                #pragma unroll
                for (int mi = 0; mi < 2; ++mi)
                    mma_tf32(acc1[mi][ni], af[mi], bf);
                if (DUAL) {
                    uint32_t bf2[2];
                    bf2[0] = __float_as_uint(B2s[buf][kk    ][n]);
                    bf2[1] = __float_as_uint(B2s[buf][kk + 4][n]);
                    #pragma unroll
                    for (int mi = 0; mi < 2; ++mi)
                        mma_tf32(acc2[mi][ni], af[mi], bf2);
                }
            }
        }
        if (it + 2 < NIT) issue((it + 2) % NST, (it + 2) * BKK);
        cp_commit();
    }

    float* Hb = g_H + (size_t)idx * TT * FF;
    #pragma unroll
    for (int mi = 0; mi < 2; ++mi) {
        #pragma unroll
        for (int rr = 0; rr < 2; ++rr) {
            int m = m0 + wm * 32 + mi * 16 + g + rr * 8;
            if (m >= Nt) continue;
            float* hrow = Hb + (size_t)m * FF + n0 + wn * 32;
            #pragma unroll
            for (int ni = 0; ni < 4; ++ni) {
                #pragma unroll
                for (int cc = 0; cc < 2; ++cc) {
                    float h1 = acc1[mi][ni][rr * 2 + cc];
                    float h;
                    if (DUAL) {
                        float h2 = acc2[mi][ni][rr * 2 + cc];
                        float sg = 1.f / (1.f + expf(-h2));
                        h = h2 * sg * h2 * h1;                       // silu(h2)*h2*h1
                    } else if (act == 1) {
                        h = 0.5f * h1 * (1.f + erff(h1 * 0.70710678118654752f));
                    } else {
                        h = fmaxf(h1, 0.f);
                    }
                    hrow[ni * 8 + 2 * tig + cc] = h;
                }
            }
        }
    }
}

// GEMM2: Z = x_gathered + H @ W3.  128x128 block, 512 threads.
__global__ void __launch_bounds__(NTH, 1) gemm2_mma_kernel(
    const float* __restrict__ x, const float* __restrict__ W3)
{
    int idx = blockIdx.z;
    int Nt = g_cnt[idx];
    int m0 = blockIdx.y * BM1;
    if (m0 >= Nt) return;
    int n0 = blockIdx.x * BN1;
    const float* Ab  = g_H + (size_t)idx * TT * FF;
    const float* W3b = W3  + (size_t)idx * FF * DD;

    extern __shared__ float smem[];
    float (*As)[BM1][APAD] = (float (*)[BM1][APAD])smem;
    float (*Bs)[BKK][BPAD] = (float (*)[BKK][BPAD])(smem + NST * BM1 * APAD);
    __shared__ int stok[BM1];

    int tid = threadIdx.x;
    int lane = tid & 31;
    int g = lane >> 2, tig = lane & 3;
    int w = tid >> 5, wm = w & 3, wn = w >> 2;

    int arow = tid >> 3, acol = (tid & 7) << 2;
    int brr  = tid >> 4, bcc  = (tid & 15) << 2;

    if (tid < BM1) {
        int m = m0 + tid;
        stok[tid] = (m < Nt) ? g_tok[idx * TT + m] : 0;
    }

    float acc[2][4][4] = {};

    auto issue = [&](int st, int k0) {
        cp16((uint32_t)__cvta_generic_to_shared(&As[st][arow][acol]),
             Ab + (size_t)(m0 + arow) * FF + k0 + acol);
        cp16((uint32_t)__cvta_generic_to_shared(&As[st][arow + 64][acol]),
             Ab + (size_t)(m0 + arow + 64) * FF + k0 + acol);
        cp16((uint32_t)__cvta_generic_to_shared(&Bs[st][brr][bcc]),
             W3b + (size_t)(k0 + brr) * DD + n0 + bcc);
        cp16((uint32_t)__cvta_generic_to_shared(&Bs[st][brr][bcc + 64]),
             W3b + (size_t)(k0 + brr) * DD + n0 + bcc + 64);
    };

    const int NIT = FF / BKK;       // 64
    issue(0, 0);    cp_commit();
    issue(1, BKK);  cp_commit();

    for (int it = 0; it < NIT; ++it) {
        cp_wait1();
        __syncthreads();
        int buf = it % NST;
        #pragma unroll
        for (int s = 0; s < 4; ++s) {
            int kk = s * 8 + tig;
            uint32_t af[2][4];
            #pragma unroll
            for (int mi = 0; mi < 2; ++mi) {
                int r = wm * 32 + mi * 16 + g;
                af[mi][0] = __float_as_uint(As[buf][r    ][kk    ]);
                af[mi][1] = __float_as_uint(As[buf][r + 8][kk    ]);
                af[mi][2] = __float_as_uint(As[buf][r    ][kk + 4]);
                af[mi][3] = __float_as_uint(As[buf][r + 8][kk + 4]);
            }
            #pragma unroll
            for (int ni = 0; ni < 4; ++ni) {
                int n = wn * 32 + ni * 8 + g;
                uint32_t bf[2];
                bf[0] = __float_as_uint(Bs[buf][kk    ][n]);
                bf[1] = __float_as_uint(Bs[buf][kk + 4][n]);
                #pragma unroll
                for (int mi = 0; mi < 2; ++mi)
                    mma_tf32(acc[mi][ni], af[mi], bf);
            }
        }
        if (it + 2 < NIT) issue((it + 2) % NST, (it + 2) * BKK);
        cp_commit();
    }

    float* Zb = g_Z + (size_t)idx * TT * DD;
    #pragma unroll
    for (int mi = 0; mi < 2; ++mi) {
        #pragma unroll
        for (int rr = 0; rr < 2; ++rr) {
            int mloc = wm * 32 + mi * 16 + g + rr * 8;
            int m = m0 + mloc;
            if (m >= Nt) continue;
            int tk = stok[mloc];
            const float* xr = x + (size_t)tk * DD + n0 + wn * 32;
            float* zrow = Zb + (size_t)m * DD + n0 + wn * 32;
            #pragma unroll
            for (int ni = 0; ni < 4; ++ni) {
                #pragma unroll
                for (int cc = 0; cc < 2; ++cc) {
                    int col = ni * 8 + 2 * tig + cc;
                    zrow[col] = acc[mi][ni][rr * 2 + cc] + xr[col];
                }
            }
        }
    }
}

// fused: per-row expert LayerNorm + expert combine + cluster LN + gate sum
__global__ void final_kernel(const float* __restrict__ loutg, const float* __restrict__ loutb,
                             const float* __restrict__ clng, const float* __restrict__ clnb,
                             float* __restrict__ out)
{
    int t = blockIdx.x;
    int tid = threadIdx.x;                    // 256
    __shared__ float rbuf[18];
    float o[4] = {};
    #pragma unroll
    for (int sI = 0; sI < 2; sI++) {
        float vcmb[4] = {};
        #pragma unroll
        for (int q = 0; q < 2; q++) {
            int slot = g_islot[t * 4 + sI * 2 + q];
            int pos  = g_ipos [t * 4 + sI * 2 + q];
            float cf = g_icoef[t * 4 + sI * 2 + q];
            const float* y = g_Z + ((size_t)slot * TT + pos) * DD;
            const float* gp = loutg + (size_t)slot * DD;
            const float* bp = loutb + (size_t)slot * DD;
            float v[4], s = 0.f, s2 = 0.f;
            #pragma unroll
            for (int r = 0; r < 4; r++) {
                int d = tid + 256 * r;
                v[r] = y[d]; s += v[r]; s2 += v[r] * v[r];
            }
            float mu, rs;
            block_meanvar_256(s, s2, rbuf, mu, rs);
            #pragma unroll
            for (int r = 0; r < 4; r++) {
                int d = tid + 256 * r;
                vcmb[r] += cf * ((v[r] - mu) * rs * gp[d] + bp[d]);
            }
        }
        float s = 0.f, s2 = 0.f;
        #pragma unroll
        for (int r = 0; r < 4; r++) { s += vcmb[r]; s2 += vcmb[r] * vcmb[r]; }
        float mu, rs;
        block_meanvar_256(s, s2, rbuf, mu, rs);
        int cc = g_sel[t * 2 + sI];
        float gt = g_gate[t * 2 + sI];
        #pragma unroll
        for (int r = 0; r < 4; r++) {
            int d = tid + 256 * r;
            o[r] += gt * ((vcmb[r] - mu) * rs * clng[cc * DD + d] + clnb[cc * DD + d]);
        }
    }
    #pragma unroll
    for (int r = 0; r < 4; r++)
        out[(size_t)t * DD + tid + 256 * r] = o[r];
}

// ---------------- launcher ----------------
extern "C" void kernel_launch(void* const* d_in, const int* in_sizes, int n_in,
                              void* d_out, int out_size)
{
    const float* x     = (const float*)d_in[0];
    const float* W1    = (const float*)d_in[1];
    const float* W2    = (const float*)d_in[2];
    const float* W3    = (const float*)d_in[3];
    const float* ling  = (const float*)d_in[4];
    const float* linb  = (const float*)d_in[5];
    const float* loutg = (const float*)d_in[6];
    const float* loutb = (const float*)d_in[7];
    const float* clng  = (const float*)d_in[8];
    const float* clnb  = (const float*)d_in[9];
    const float* Wrc   = (const float*)d_in[10];
    const float* brc   = (const float*)d_in[11];
    const float* Wre   = (const float*)d_in[12];
    const float* bre   = (const float*)d_in[13];
    float* out = (float*)d_out;

    const int SM_DUAL = (NST * BM1 * APAD + 2 * NST * BKK * BPAD) * 4;  // 159744
    const int SM_SNGL = (NST * BM1 * APAD +     NST * BKK * BPAD) * 4;  // 107520

    cudaFuncSetAttribute(gemm1_mma_kernel<true>,
                         cudaFuncAttributeMaxDynamicSharedMemorySize, SM_DUAL);
    cudaFuncSetAttribute(gemm1_mma_kernel<false>,
                         cudaFuncAttributeMaxDynamicSharedMemorySize, SM_SNGL);
    cudaFuncSetAttribute(gemm2_mma_kernel,
                         cudaFuncAttributeMaxDynamicSharedMemorySize, SM_SNGL);

    zero_cnt_kernel<<<1, 32>>>();
    routing_kernel<<<TT, 128>>>(x, Wrc, brc, Wre, bre);

    dim3 gp(TT, NEXP);
    prep_kernel<<<gp, 256>>>(x, ling, linb);

    dim3 g1(FF / BN1, TT / BM1, 8);
    gemm1_mma_kernel<true ><<<g1, NTH, SM_DUAL>>>(W1, W2);
    gemm1_mma_kernel<false><<<g1, NTH, SM_SNGL>>>(W1, W2);

    dim3 g2(DD / BN1, TT / BM1, NEXP);
    gemm2_mma_kernel<<<g2, NTH, SM_SNGL>>>(x, W3);

    final_kernel<<<TT, 256>>>(loutg, loutb, clng, clnb, out);
}

// round 7
// speedup vs baseline: 1.0254x; 1.0254x over previous
#include <cuda_runtime.h>
#include <math.h>
#include <stdint.h>

#define TT 2048
#define DD 1024
#define FF 2048
#define CC 4
#define EE 4
#define NEXP 16
#define EPSL 1e-5f

// mma.sync fallback tile params
#define BM1 128
#define BN1 128
#define BKK 32
#define NST 3
#define APAD 36
#define BPAD 136
#define NTH 512

// Arch-specific ('a') feature gate: tcgen05 only exists when the virtual arch
// is compute_103a/compute_100a. Fail closed (0) everywhere else.
#if defined(__CUDA_ARCH_FEAT_SM103_ALL) || defined(__CUDA_ARCH_FEAT_SM100_ALL) || \
    (defined(__CUDA_ARCH_SPECIFIC__) && (__CUDA_ARCH_SPECIFIC__ >= 1000))
#define TC_OK 1
#else
#define TC_OK 0
#endif

// ---------------- device scratch ----------------
__device__ float g_A[16ULL*2048ULL*1024ULL];   // LN'd gathered rows (tf32-rounded)
__device__ float g_H[16ULL*2048ULL*2048ULL];   // activated hidden
__device__ float g_Z[16ULL*2048ULL*1024ULL];   // expert outputs (+residual, pre-LN)
__device__ float g_W1t[16ULL*2048ULL*1024ULL]; // W1^T: [idx][F][D]   (tc path only)
__device__ float g_W2t[16ULL*2048ULL*1024ULL]; // W2^T: [idx][F][D]   (tc path only)
__device__ float g_W3t[16ULL*1024ULL*2048ULL]; // W3^T: [idx][D][F]   (tc path only)
__device__ int   g_cnt[NEXP];
__device__ int   g_tok[NEXP*TT];
__device__ float g_mu[TT];
__device__ float g_rstd[TT];
__device__ int   g_sel[TT*2];
__device__ float g_gate[TT*2];
__device__ int   g_islot[TT*4];
__device__ int   g_ipos[TT*4];
__device__ float g_icoef[TT*4];

// ---------------- helpers ----------------
__device__ __forceinline__ float tf32r(float f) {
    uint32_t r;
    asm("cvt.rna.tf32.f32 %0, %1;" : "=r"(r) : "f"(f));
    return __uint_as_float(r);
}
__device__ __forceinline__ void mma_tf32(float* c, const uint32_t* a, const uint32_t* b) {
    asm volatile(
        "mma.sync.aligned.m16n8k8.row.col.f32.tf32.tf32.f32 "
        "{%0,%1,%2,%3}, {%4,%5,%6,%7}, {%8,%9}, {%0,%1,%2,%3};\n"
        : "+f"(c[0]), "+f"(c[1]), "+f"(c[2]), "+f"(c[3])
        : "r"(a[0]), "r"(a[1]), "r"(a[2]), "r"(a[3]), "r"(b[0]), "r"(b[1]));
}
__device__ __forceinline__ void cp16(uint32_t dst, const void* src) {
    asm volatile("cp.async.cg.shared.global [%0], [%1], 16;\n" :: "r"(dst), "l"(src));
}
__device__ __forceinline__ void cp_commit() {
    asm volatile("cp.async.commit_group;\n" ::: "memory");
}
__device__ __forceinline__ void cp_wait1() {
    asm volatile("cp.async.wait_group 1;\n" ::: "memory");
}
template<int N>
__device__ __forceinline__ void cp_waitn() {
    asm volatile("cp.async.wait_group %0;\n" :: "n"(N) : "memory");
}
__device__ __forceinline__ uint32_t smem_u32(const void* p) {
    uint32_t a;
    asm("{ .reg .u64 t; cvta.to.shared.u64 t, %1; cvt.u32.u64 %0, t; }" : "=r"(a) : "l"(p));
    return a;
}

#define SWZ128(off) ((off) ^ (((off) >> 3) & 0x70))

// ---------------- block mean/var (256 threads) ----------------
__device__ __forceinline__ void block_meanvar_256(float s, float s2, float* rbuf,
                                                  float& mu, float& rs)
{
    int tid = threadIdx.x, lane = tid & 31, w = tid >> 5;
    __syncthreads();
    #pragma unroll
    for (int o = 16; o; o >>= 1) {
        s  += __shfl_down_sync(0xffffffffu, s,  o);
        s2 += __shfl_down_sync(0xffffffffu, s2, o);
    }
    if (lane == 0) { rbuf[w] = s; rbuf[8 + w] = s2; }
    __syncthreads();
    if (tid == 0) {
        float S = 0.f, S2 = 0.f;
        #pragma unroll
        for (int ww = 0; ww < 8; ww++) { S += rbuf[ww]; S2 += rbuf[8 + ww]; }
        float m = S / (float)DD;
        rbuf[16] = m;
        rbuf[17] = rsqrtf(S2 / (float)DD - m * m + EPSL);
    }
    __syncthreads();
    mu = rbuf[16];
    rs = rbuf[17];
}

// ---------------- small kernels (shared by both paths) ----------------
__global__ void zero_cnt_kernel()
{
    if (threadIdx.x < NEXP) g_cnt[threadIdx.x] = 0;
}

__global__ void routing_kernel(const float* __restrict__ x,
                               const float* __restrict__ Wrc, const float* __restrict__ brc,
                               const float* __restrict__ Wre, const float* __restrict__ bre)
{
    int t = blockIdx.x;
    __shared__ float xs[DD];
    __shared__ float rbuf[16];
    __shared__ float lgs[20];
    int tid = threadIdx.x;          // 128 threads
    int lane = tid & 31, wid = tid >> 5;

    float s = 0.f, s2 = 0.f;
    for (int d = tid; d < DD; d += 128) {
        float v = x[(size_t)t * DD + d];
        xs[d] = v; s += v; s2 += v * v;
    }
    #pragma unroll
    for (int o = 16; o; o >>= 1) {
        s  += __shfl_down_sync(0xffffffffu, s,  o);
        s2 += __shfl_down_sync(0xffffffffu, s2, o);
    }
    if (lane == 0) { rbuf[wid] = s; rbuf[8 + wid] = s2; }
    __syncthreads();
    if (tid == 0) {
        float S  = rbuf[0] + rbuf[1] + rbuf[2] + rbuf[3];
        float S2 = rbuf[8] + rbuf[9] + rbuf[10] + rbuf[11];
        float mu = S / (float)DD;
        float var = S2 / (float)DD - mu * mu;
        g_mu[t] = mu;
        g_rstd[t] = rsqrtf(var + EPSL);
    }

    for (int v = wid; v < 20; v += 4) {
        float acc = 0.f;
        if (v < CC) {
            for (int d = lane; d < DD; d += 32) acc += xs[d] * Wrc[d * CC + v];
        } else {
            int cc = (v - 4) >> 2, e = (v - 4) & 3;
            const float* wp = Wre + (size_t)cc * DD * EE + e;
            for (int d = lane; d < DD; d += 32) acc += xs[d] * wp[d * EE];
        }
        #pragma unroll
        for (int o = 16; o; o >>= 1) acc += __shfl_down_sync(0xffffffffu, acc, o);
        if (lane == 0) lgs[v] = acc;
    }
    __syncthreads();

    if (tid == 0) {
        float p[CC];
        float mx = -1e30f;
        for (int c = 0; c < CC; c++) { p[c] = lgs[c] + brc[c]; mx = fmaxf(mx, p[c]); }
        float ss = 0.f;
        for (int c = 0; c < CC; c++) { p[c] = expf(p[c] - mx); ss += p[c]; }
        for (int c = 0; c < CC; c++) p[c] /= ss;
        int i0 = 0;
        for (int c = 1; c < CC; c++) if (p[c] > p[i0]) i0 = c;
        int i1 = -1;
        for (int c = 0; c < CC; c++) if (c != i0 && (i1 < 0 || p[c] > p[i1])) i1 = c;
        float swt = p[i0] + p[i1];
        int sel[2] = { i0, i1 };
        float gv[2] = { p[i0] / swt, p[i1] / swt };

        for (int sI = 0; sI < 2; sI++) {
            int cc = sel[sI];
            g_sel[t * 2 + sI]  = cc;
            g_gate[t * 2 + sI] = gv[sI];
            float el[EE];
            for (int e = 0; e < EE; e++) el[e] = lgs[4 + cc * 4 + e] + bre[cc * EE + e];
            int e0 = 0;
            for (int e = 1; e < EE; e++) if (el[e] > el[e0]) e0 = e;
            int e1 = -1;
            for (int e = 0; e < EE; e++) if (e != e0 && (e1 < 0 || el[e] > el[e1])) e1 = e;
            float z = expf(el[e1] - el[e0]);
            float w0 = 1.f / (1.f + z), w1 = z / (1.f + z);
            int   eS[2] = { e0, e1 };
            float wS[2] = { w0, w1 };
            for (int q = 0; q < 2; q++) {
                int slot = cc * EE + eS[q];
                int pos = atomicAdd(&g_cnt[slot], 1);
                g_tok[slot * TT + pos] = t;
                g_islot[t * 4 + sI * 2 + q] = slot;
                g_ipos [t * 4 + sI * 2 + q] = pos;
                g_icoef[t * 4 + sI * 2 + q] = wS[q];
            }
        }
    }
}

__global__ void prep_kernel(const float* __restrict__ x,
                            const float* __restrict__ ling, const float* __restrict__ linb)
{
    int idx = blockIdx.y;
    int i = blockIdx.x;
    if (i >= g_cnt[idx]) return;
    int tok = g_tok[idx * TT + i];
    float mu = g_mu[tok], rs = g_rstd[tok];
    const float4* xr = (const float4*)(x + (size_t)tok * DD);
    const float4* gp = (const float4*)(ling + (size_t)idx * DD);
    const float4* bp = (const float4*)(linb + (size_t)idx * DD);
    float4* ar = (float4*)(g_A + ((size_t)idx * TT + i) * DD);
    int d = threadIdx.x;           // 256 threads
    float4 xv = xr[d], gv = gp[d], bv = bp[d];
    float4 o;
    o.x = tf32r((xv.x - mu) * rs * gv.x + bv.x);
    o.y = tf32r((xv.y - mu) * rs * gv.y + bv.y);
    o.z = tf32r((xv.z - mu) * rs * gv.z + bv.z);
    o.w = tf32r((xv.w - mu) * rs * gv.w + bv.w);
    ar[d] = o;
}

// weight transpose: in [z][R][C] -> out [z][C][R], tf32-rounded (tc path only)
__global__ void transpose_kernel(const float* __restrict__ in, float* __restrict__ out,
                                 int R, int C, int dualmap)
{
    __shared__ float t[32][33];
    int z = blockIdx.z;
    int idx = dualmap ? ((z >> 1) * 4 + ((z & 1) ? 3 : 0)) : z;
    const float* ip = in + (size_t)idx * R * C;
    float* op = out + (size_t)idx * R * C;
    int c0 = blockIdx.x * 32, r0 = blockIdx.y * 32;
    int tx = threadIdx.x & 31, ty = threadIdx.x >> 5;   // 256 threads
    #pragma unroll
    for (int i = 0; i < 4; i++)
        t[ty + 8 * i][tx] = tf32r(ip[(size_t)(r0 + ty + 8 * i) * C + c0 + tx]);
    __syncthreads();
    #pragma unroll
    for (int i = 0; i < 4; i++)
        op[(size_t)(c0 + ty + 8 * i) * R + r0 + tx] = t[tx][ty + 8 * i];
}

// ======================= tcgen05 path (only real under 'a' arch) =======================
#if TC_OK
static constexpr uint64_t SMEM_DESC_BASE_SW128 =
    (uint64_t(2)  << 61) | (uint64_t(1) << 46) | (uint64_t(64) << 32) | (uint64_t(1) << 16);
#define MAKE_SMEM_DESC(base_addr) \
    (SMEM_DESC_BASE_SW128 | ((uint64_t)((base_addr) >> 4) & 0x3FFF))

// idesc: dtype=F32(1), atype=btype=TF32(2), N=128, M=128
#define IDESC_TF32_N128 ((1u<<4) | (2u<<7) | (2u<<10) | ((128u/8u)<<17) | ((128u/16u)<<24))

__device__ __forceinline__ void umma_tf32(uint32_t d_tmem, uint64_t a_desc,
                                          uint64_t b_desc, uint32_t idesc, uint32_t en)
{
    asm volatile(
        "{\n\t"
        ".reg .pred p;\n\t"
        "setp.ne.u32 p, %5, 0;\n\t"
        "tcgen05.mma.cta_group::1.kind::tf32 [%0], %1, %2, %3, {%4, %4, %4, %4}, p;\n\t"
        "}"
        :: "r"(d_tmem), "l"(a_desc), "l"(b_desc), "r"(idesc), "r"(0u), "r"(en)
        : "memory");
}
__device__ __forceinline__ uint32_t elect_one_pred() {
    uint32_t pred;
    asm volatile(
        "{\n\t.reg .pred p;\n\telect.sync _|p, 0xFFFFFFFF;\n\tselp.b32 %0, 1, 0, p;\n\t}"
        : "=r"(pred));
    return pred;
}
__device__ __forceinline__ void fence_proxy_async() {
    asm volatile("fence.proxy.async;" ::: "memory");
}
#define TCGEN05_ALLOC(sa, n) \
    asm volatile("tcgen05.alloc.cta_group::1.sync.aligned.shared::cta.b32 [%0], %1;" \
        :: "r"((uint32_t)(sa)), "r"((uint32_t)(n)) : "memory")
#define TCGEN05_DEALLOC(t, n) \
    asm volatile("tcgen05.dealloc.cta_group::1.sync.aligned.b32 %0, %1;" \
        :: "r"(t), "r"((uint32_t)(n)))
#define TCGEN05_RELINQUISH() \
    asm volatile("tcgen05.relinquish_alloc_permit.cta_group::1.sync.aligned;")
#define TCGEN05_COMMIT(mb) \
    asm volatile("tcgen05.commit.cta_group::1.mbarrier::arrive::one.shared::cluster.b64 [%0];" \
        :: "r"((uint32_t)(mb)) : "memory")
#define TCGEN05_FENCE_AFTER() \
    asm volatile("tcgen05.fence::after_thread_sync;" ::: "memory")
#define TCGEN05_WAIT_LD() \
    asm volatile("tcgen05.wait::ld.sync.aligned;" ::: "memory")
#define TCGEN05_LD_X16(r, ta) \
    asm volatile( \
        "tcgen05.ld.sync.aligned.32x32b.x16.b32 " \
        "{%0, %1, %2, %3, %4, %5, %6, %7, " \
        " %8, %9, %10, %11, %12, %13, %14, %15}, [%16];" \
        : "=r"((r)[0]),  "=r"((r)[1]),  "=r"((r)[2]),  "=r"((r)[3]), \
          "=r"((r)[4]),  "=r"((r)[5]),  "=r"((r)[6]),  "=r"((r)[7]), \
          "=r"((r)[8]),  "=r"((r)[9]),  "=r"((r)[10]), "=r"((r)[11]), \
          "=r"((r)[12]), "=r"((r)[13]), "=r"((r)[14]), "=r"((r)[15]) \
        : "r"(ta))
#define MBARRIER_INIT(mb, c) \
    asm volatile("mbarrier.init.shared.b64 [%0], %1;" \
        :: "r"((uint32_t)(mb)), "r"((uint32_t)(c)) : "memory")
#define MBARRIER_INVAL(mb) \
    asm volatile("mbarrier.inval.shared.b64 [%0];" :: "r"((uint32_t)(mb)) : "memory")
#define MBAR_WAIT(mb, parity) do { \
    uint32_t _m = (uint32_t)(mb); \
    uint32_t _p = (uint32_t)(parity); \
    uint32_t _done; \
    asm volatile( \
        "{\n\t.reg .pred p;\n\t" \
        "mbarrier.try_wait.parity.acquire.cta.shared::cta.b64 p, [%1], %2;\n\t" \
        "selp.b32 %0, 1, 0, p;\n\t}" \
        : "=r"(_done) : "r"(_m), "r"(_p) : "memory"); \
    if (!_done) { \
        asm volatile( \
            "{\n\t.reg .pred P1;\n\t" \
            "WAIT_LOOP_%=:\n\t" \
            "mbarrier.try_wait.parity.acquire.cta.shared::cta.b64 P1, [%0], %1, 0x989680;\n\t" \
            "@P1 bra.uni WAIT_DONE_%=;\n\t" \
            "bra.uni WAIT_LOOP_%=;\n\t" \
            "WAIT_DONE_%=:\n\t}" \
            :: "r"(_m), "r"(_p) : "memory"); \
    } \
} while (0)
#endif  // TC_OK

// tc GEMM1: H = act( A @ W1t^T [, @ W2t^T] ). Tile 128m x 256n, K-chunk 32.
template<bool DUAL, int NSTG>
__global__ void __launch_bounds__(512, 1)
gemm1_tc_kernel(const float* __restrict__ W1t, const float* __restrict__ W2t)
{
#if TC_OK
    int z = blockIdx.z;
    int idx = DUAL ? ((z >> 1) * 4 + ((z & 1) ? 3 : 0))
                   : ((z >> 1) * 4 + ((z & 1) ? 2 : 1));
    int Nt = g_cnt[idx];
    int m0 = blockIdx.y * 128;
    if (m0 >= Nt) return;
    int n0 = blockIdx.x * 256;
    const float* Ab  = g_A  + (size_t)idx * TT * DD;
    const float* B1g = W1t + (size_t)idx * DD * FF;   // [F][D]
    const float* B2g = W2t + (size_t)idx * DD * FF;

    extern __shared__ __align__(1024) char smem[];
    uint32_t sb = smem_u32(smem);
    const uint32_t ASZ = 128u * 128u;     // 16KB per stage
    const uint32_t BSZ = 256u * 128u;     // 32KB per stage
    uint32_t aBase  = sb;
    uint32_t b1Base = sb + NSTG * ASZ;
    uint32_t b2Base = b1Base + NSTG * BSZ;
    uint32_t ctrl   = b1Base + NSTG * BSZ * (DUAL ? 2 : 1);

    int tid = threadIdx.x;
    int w = tid >> 5;

    if (w == 0) TCGEN05_ALLOC(ctrl, DUAL ? 512 : 256);
    if (tid == 0) MBARRIER_INIT(ctrl + 8, 1);
    __syncthreads();
    uint32_t tmem;
    asm volatile("ld.shared.b32 %0, [%1];" : "=r"(tmem) : "r"(ctrl));

    auto load_chunk = [&](int st, int ch) {
        int k0 = ch * 32;
        #pragma unroll
        for (int i = 0; i < 2; ++i) {
            int lin = tid + 512 * i;
            int row = lin >> 3, c16 = lin & 7;
            uint32_t off = (uint32_t)(row * 128 + c16 * 16);
            cp16(aBase + st * ASZ + SWZ128(off),
                 Ab + (size_t)(m0 + row) * DD + k0 + c16 * 4);
        }
        #pragma unroll
        for (int i = 0; i < 4; ++i) {
            int lin = tid + 512 * i;
            int row = lin >> 3, c16 = lin & 7;
            uint32_t off = (uint32_t)(row * 128 + c16 * 16);
            size_t gs = (size_t)(n0 + row) * DD + k0 + c16 * 4;
            cp16(b1Base + st * BSZ + SWZ128(off), B1g + gs);
            if (DUAL) cp16(b2Base + st * BSZ + SWZ128(off), B2g + gs);
        }
    };

    const int NCH = DD / 32;   // 32
    #pragma unroll
    for (int p = 0; p < NSTG; ++p) { load_chunk(p, p); cp_commit(); }

    uint32_t ph = 0;
    for (int it = 0; it < NCH; ++it) {
        int buf = it % NSTG;
        cp_waitn<NSTG - 1>();
        __syncthreads();
        if (w == 0 && elect_one_pred()) {
            fence_proxy_async();
            uint64_t ad = MAKE_SMEM_DESC(aBase + buf * ASZ);
            #pragma unroll
            for (int half = 0; half < 2; ++half) {
                uint64_t bd = MAKE_SMEM_DESC(b1Base + buf * BSZ + half * 16384u);
                #pragma unroll
                for (int k = 0; k < 4; ++k)
                    umma_tf32(tmem + half * 128, ad + 2 * k, bd + 2 * k,
                              IDESC_TF32_N128, (uint32_t)(it > 0 || k > 0));
            }
            if (DUAL) {
                #pragma unroll
                for (int half = 0; half < 2; ++half) {
                    uint64_t bd2 = MAKE_SMEM_DESC(b2Base + buf * BSZ + half * 16384u);
                    #pragma unroll
                    for (int k = 0; k < 4; ++k)
                        umma_tf32(tmem + 256 + half * 128, ad + 2 * k, bd2 + 2 * k,
                                  IDESC_TF32_N128, (uint32_t)(it > 0 || k > 0));
                }
            }
            TCGEN05_COMMIT(ctrl + 8);
        }
        MBAR_WAIT(ctrl + 8, ph); ph ^= 1;
        if (it + NSTG < NCH) load_chunk(buf, it + NSTG);
        cp_commit();
    }
    TCGEN05_FENCE_AFTER();

    int lane = tid & 31;
    int sub = w & 3, grp = w >> 2;
    int mrow = m0 + sub * 32 + lane;
    bool valid = mrow < Nt;
    int act = (idx & 3) % 3;
    float* Hb = g_H + (size_t)idx * TT * FF;
    #pragma unroll
    for (int cc = 0; cc < 4; ++cc) {
        int col = grp * 64 + cc * 16;
        uint32_t d1[16], d2[16];
        TCGEN05_LD_X16(d1, tmem + col);
        if (DUAL) { TCGEN05_LD_X16(d2, tmem + 256 + col); }
        TCGEN05_WAIT_LD();
        float h[16];
        #pragma unroll
        for (int r = 0; r < 16; ++r) {
            float h1 = __uint_as_float(d1[r]);
            float hv;
            if (DUAL) {
                float h2 = __uint_as_float(d2[r]);
                float sg = 1.f / (1.f + expf(-h2));
                hv = h2 * sg * h2 * h1;                       // silu(h2)*h2*h1
            } else if (act == 1) {
                hv = 0.5f * h1 * (1.f + erff(h1 * 0.70710678118654752f));
            } else {
                hv = fmaxf(h1, 0.f);
            }
            h[r] = tf32r(hv);
        }
        if (valid) {
            float4* p = (float4*)(Hb + (size_t)mrow * FF + n0 + col);
            #pragma unroll
            for (int v = 0; v < 4; ++v)
                p[v] = make_float4(h[4*v], h[4*v+1], h[4*v+2], h[4*v+3]);
        }
    }
    __syncthreads();
    if (tid == 0) MBARRIER_INVAL(ctrl + 8);
    if (w == 0) { TCGEN05_RELINQUISH(); TCGEN05_DEALLOC(tmem, DUAL ? 512 : 256); }
#endif
}

// tc GEMM2: Z = x + H @ W3t^T. Tile 128m x 256n.
template<int NSTG>
__global__ void __launch_bounds__(512, 1)
gemm2_tc_kernel(const float* __restrict__ x, const float* __restrict__ W3t)
{
#if TC_OK
    int idx = blockIdx.z;
    int Nt = g_cnt[idx];
    int m0 = blockIdx.y * 128;
    if (m0 >= Nt) return;
    int n0 = blockIdx.x * 256;
    const float* Ab = g_H  + (size_t)idx * TT * FF;
    const float* Bg = W3t + (size_t)idx * DD * FF;   // [D][F]

    extern __shared__ __align__(1024) char smem[];
    uint32_t sb = smem_u32(smem);
    const uint32_t ASZ = 128u * 128u;
    const uint32_t BSZ = 256u * 128u;
    uint32_t aBase = sb;
    uint32_t bBase = sb + NSTG * ASZ;
    uint32_t ctrl  = bBase + NSTG * BSZ;

    int tid = threadIdx.x;
    int w = tid >> 5;

    if (w == 0) TCGEN05_ALLOC(ctrl, 256);
    if (tid == 0) MBARRIER_INIT(ctrl + 8, 1);
    __syncthreads();
    uint32_t tmem;
    asm volatile("ld.shared.b32 %0, [%1];" : "=r"(tmem) : "r"(ctrl));

    auto load_chunk = [&](int st, int ch) {
        int k0 = ch * 32;
        #pragma unroll
        for (int i = 0; i < 2; ++i) {
            int lin = tid + 512 * i;
            int row = lin >> 3, c16 = lin & 7;
            uint32_t off = (uint32_t)(row * 128 + c16 * 16);
            cp16(aBase + st * ASZ + SWZ128(off),
                 Ab + (size_t)(m0 + row) * FF + k0 + c16 * 4);
        }
        #pragma unroll
        for (int i = 0; i < 4; ++i) {
            int lin = tid + 512 * i;
            int row = lin >> 3, c16 = lin & 7;
            uint32_t off = (uint32_t)(row * 128 + c16 * 16);
            cp16(bBase + st * BSZ + SWZ128(off),
                 Bg + (size_t)(n0 + row) * FF + k0 + c16 * 4);
        }
    };

    const int NCH = FF / 32;   // 64
    #pragma unroll
    for (int p = 0; p < NSTG; ++p) { load_chunk(p, p); cp_commit(); }

    uint32_t ph = 0;
    for (int it = 0; it < NCH; ++it) {
        int buf = it % NSTG;
        cp_waitn<NSTG - 1>();
        __syncthreads();
        if (w == 0 && elect_one_pred()) {
            fence_proxy_async();
            uint64_t ad = MAKE_SMEM_DESC(aBase + buf * ASZ);
            #pragma unroll
            for (int half = 0; half < 2; ++half) {
                uint64_t bd = MAKE_SMEM_DESC(bBase + buf * BSZ + half * 16384u);
                #pragma unroll
                for (int k = 0; k < 4; ++k)
                    umma_tf32(tmem + half * 128, ad + 2 * k, bd + 2 * k,
                              IDESC_TF32_N128, (uint32_t)(it > 0 || k > 0));
            }
            TCGEN05_COMMIT(ctrl + 8);
        }
        MBAR_WAIT(ctrl + 8, ph); ph ^= 1;
        if (it + NSTG < NCH) load_chunk(buf, it + NSTG);
        cp_commit();
    }
    TCGEN05_FENCE_AFTER();

    int lane = tid & 31;
    int sub = w & 3, grp = w >> 2;
    int mrow = m0 + sub * 32 + lane;
    bool valid = mrow < Nt;
    int tok = valid ? g_tok[idx * TT + mrow] : 0;
    float* Zb = g_Z + (size_t)idx * TT * DD;
    #pragma unroll
    for (int cc = 0; cc < 4; ++cc) {
        int col = grp * 64 + cc * 16;
        uint32_t d1[16];
        TCGEN05_LD_X16(d1, tmem + col);
        TCGEN05_WAIT_LD();
        if (valid) {
            const float4* xr = (const float4*)(x + (size_t)tok * DD + n0 + col);
            float4* p = (float4*)(Zb + (size_t)mrow * DD + n0 + col);
            #pragma unroll
            for (int v = 0; v < 4; ++v) {
                float4 xv = xr[v];
                p[v] = make_float4(__uint_as_float(d1[4*v])   + xv.x,
                                   __uint_as_float(d1[4*v+1]) + xv.y,
                                   __uint_as_float(d1[4*v+2]) + xv.z,
                                   __uint_as_float(d1[4*v+3]) + xv.w);
            }
        }
    }
    __syncthreads();
    if (tid == 0) MBARRIER_INVAL(ctrl + 8);
    if (w == 0) { TCGEN05_RELINQUISH(); TCGEN05_DEALLOC(tmem, 256); }
#endif
}

// ======================= mma.sync fallback (R4, proven 727us) =======================
template<bool DUAL>
__global__ void __launch_bounds__(NTH, 1) gemm1_mma_kernel(
    const float* __restrict__ W1, const float* __restrict__ W2)
{
    int z = blockIdx.z;
    int idx = DUAL ? ((z >> 1) * 4 + ((z & 1) ? 3 : 0))
                   : ((z >> 1) * 4 + ((z & 1) ? 2 : 1));
    int Nt = g_cnt[idx];
    int m0 = blockIdx.y * BM1;
    if (m0 >= Nt) return;
    int n0 = blockIdx.x * BN1;
    int act = (idx & 3) % 3;
    const float* W1b = W1 + (size_t)idx * DD * FF;
    const float* W2b = W2 + (size_t)idx * DD * FF;
    const float* Ab  = g_A + (size_t)idx * TT * DD;

    extern __shared__ float smemf[];
    float (*As)[BM1][APAD]  = (float (*)[BM1][APAD])smemf;
    float (*B1s)[BKK][BPAD] = (float (*)[BKK][BPAD])(smemf + NST * BM1 * APAD);
    float (*B2s)[BKK][BPAD] = (float (*)[BKK][BPAD])(smemf + NST * BM1 * APAD + NST * BKK * BPAD);

    int tid = threadIdx.x;
    int lane = tid & 31;
    int g = lane >> 2, tig = lane & 3;
    int w = tid >> 5, wm = w & 3, wn = w >> 2;

    int arow = tid >> 3, acol = (tid & 7) << 2;
    int brr  = tid >> 4, bcc  = (tid & 15) << 2;

    float acc1[2][4][4] = {};
    float acc2[DUAL ? 2 : 1][4][4] = {};

    auto issue = [&](int st, int k0) {
        cp16((uint32_t)__cvta_generic_to_shared(&As[st][arow][acol]),
             Ab + (size_t)(m0 + arow) * DD + k0 + acol);
        cp16((uint32_t)__cvta_generic_to_shared(&As[st][arow + 64][acol]),
             Ab + (size_t)(m0 + arow + 64) * DD + k0 + acol);
        cp16((uint32_t)__cvta_generic_to_shared(&B1s[st][brr][bcc]),
             W1b + (size_t)(k0 + brr) * FF + n0 + bcc);
        cp16((uint32_t)__cvta_generic_to_shared(&B1s[st][brr][bcc + 64]),
             W1b + (size_t)(k0 + brr) * FF + n0 + bcc + 64);
        if (DUAL) {
            cp16((uint32_t)__cvta_generic_to_shared(&B2s[st][brr][bcc]),
                 W2b + (size_t)(k0 + brr) * FF + n0 + bcc);
            cp16((uint32_t)__cvta_generic_to_shared(&B2s[st][brr][bcc + 64]),
                 W2b + (size_t)(k0 + brr) * FF + n0 + bcc + 64);
        }
    };

    const int NIT = DD / BKK;       // 32
    issue(0, 0);          cp_commit();
    issue(1, BKK);        cp_commit();

    for (int it = 0; it < NIT; ++it) {
        cp_wait1();
        __syncthreads();
        int buf = it % NST;
        #pragma unroll
        for (int s = 0; s < 4; ++s) {
            int kk = s * 8 + tig;
            uint32_t af[2][4];
            #pragma unroll
            for (int mi = 0; mi < 2; ++mi) {
                int r = wm * 32 + mi * 16 + g;
                af[mi][0] = __float_as_uint(As[buf][r    ][kk    ]);
                af[mi][1] = __float_as_uint(As[buf][r + 8][kk    ]);
                af[mi][2] = __float_as_uint(As[buf][r    ][kk + 4]);
                af[mi][3] = __float_as_uint(As[buf][r + 8][kk + 4]);
            }
            #pragma unroll
            for (int ni = 0; ni < 4; ++ni) {
                int n = wn * 32 + ni * 8 + g;
                uint32_t bf[2];
                bf[0] = __float_as_uint(B1s[buf][kk    ][n]);
                bf[1] = __float_as_uint(B1s[buf][kk + 4][n]);
                #pragma unroll
                for (int mi = 0; mi < 2; ++mi)
                    mma_tf32(acc1[mi][ni], af[mi], bf);
                if (DUAL) {
                    uint32_t bf2[2];
                    bf2[0] = __float_as_uint(B2s[buf][kk    ][n]);
                    bf2[1] = __float_as_uint(B2s[buf][kk + 4][n]);
                    #pragma unroll
                    for (int mi = 0; mi < 2; ++mi)
                        mma_tf32(acc2[mi][ni], af[mi], bf2);
                }
            }
        }
        if (it + 2 < NIT) issue((it + 2) % NST, (it + 2) * BKK);
        cp_commit();
    }

    float* Hb = g_H + (size_t)idx * TT * FF;
    #pragma unroll
    for (int mi = 0; mi < 2; ++mi) {
        #pragma unroll
        for (int rr = 0; rr < 2; ++rr) {
            int m = m0 + wm * 32 + mi * 16 + g + rr * 8;
            if (m >= Nt) continue;
            float* hrow = Hb + (size_t)m * FF + n0 + wn * 32;
            #pragma unroll
            for (int ni = 0; ni < 4; ++ni) {
                #pragma unroll
                for (int cc = 0; cc < 2; ++cc) {
                    float h1 = acc1[mi][ni][rr * 2 + cc];
                    float h;
                    if (DUAL) {
                        float h2 = acc2[mi][ni][rr * 2 + cc];
                        float sg = 1.f / (1.f + expf(-h2));
                        h = h2 * sg * h2 * h1;
                    } else if (act == 1) {
                        h = 0.5f * h1 * (1.f + erff(h1 * 0.70710678118654752f));
                    } else {
                        h = fmaxf(h1, 0.f);
                    }
                    hrow[ni * 8 + 2 * tig + cc] = h;
                }
            }
        }
    }
}

__global__ void __launch_bounds__(NTH, 1) gemm2_mma_kernel(
    const float* __restrict__ x, const float* __restrict__ W3)
{
    int idx = blockIdx.z;
    int Nt = g_cnt[idx];
    int m0 = blockIdx.y * BM1;
    if (m0 >= Nt) return;
    int n0 = blockIdx.x * BN1;
    const float* Ab  = g_H + (size_t)idx * TT * FF;
    const float* W3b = W3  + (size_t)idx * FF * DD;

    extern __shared__ float smemf[];
    float (*As)[BM1][APAD] = (float (*)[BM1][APAD])smemf;
    float (*Bs)[BKK][BPAD] = (float (*)[BKK][BPAD])(smemf + NST * BM1 * APAD);
    __shared__ int stok[BM1];

    int tid = threadIdx.x;
    int lane = tid & 31;
    int g = lane >> 2, tig = lane & 3;
    int w = tid >> 5, wm = w & 3, wn = w >> 2;

    int arow = tid >> 3, acol = (tid & 7) << 2;
    int brr  = tid >> 4, bcc  = (tid & 15) << 2;

    if (tid < BM1) {
        int m = m0 + tid;
        stok[tid] = (m < Nt) ? g_tok[idx * TT + m] : 0;
    }

    float acc[2][4][4] = {};

    auto issue = [&](int st, int k0) {
        cp16((uint32_t)__cvta_generic_to_shared(&As[st][arow][acol]),
             Ab + (size_t)(m0 + arow) * FF + k0 + acol);
        cp16((uint32_t)__cvta_generic_to_shared(&As[st][arow + 64][acol]),
             Ab + (size_t)(m0 + arow + 64) * FF + k0 + acol);
        cp16((uint32_t)__cvta_generic_to_shared(&Bs[st][brr][bcc]),
             W3b + (size_t)(k0 + brr) * DD + n0 + bcc);
        cp16((uint32_t)__cvta_generic_to_shared(&Bs[st][brr][bcc + 64]),
             W3b + (size_t)(k0 + brr) * DD + n0 + bcc + 64);
    };

    const int NIT = FF / BKK;       // 64
    issue(0, 0);    cp_commit();
    issue(1, BKK);  cp_commit();

    for (int it = 0; it < NIT; ++it) {
        cp_wait1();
        __syncthreads();
        int buf = it % NST;
        #pragma unroll
        for (int s = 0; s < 4; ++s) {
            int kk = s * 8 + tig;
            uint32_t af[2][4];
            #pragma unroll
            for (int mi = 0; mi < 2; ++mi) {
                int r = wm * 32 + mi * 16 + g;
                af[mi][0] = __float_as_uint(As[buf][r    ][kk    ]);
                af[mi][1] = __float_as_uint(As[buf][r + 8][kk    ]);
                af[mi][2] = __float_as_uint(As[buf][r    ][kk + 4]);
                af[mi][3] = __float_as_uint(As[buf][r + 8][kk + 4]);
            }
            #pragma unroll
            for (int ni = 0; ni < 4; ++ni) {
                int n = wn * 32 + ni * 8 + g;
                uint32_t bf[2];
                bf[0] = __float_as_uint(Bs[buf][kk    ][n]);
                bf[1] = __float_as_uint(Bs[buf][kk + 4][n]);
                #pragma unroll
                for (int mi = 0; mi < 2; ++mi)
                    mma_tf32(acc[mi][ni], af[mi], bf);
            }
        }
        if (it + 2 < NIT) issue((it + 2) % NST, (it + 2) * BKK);
        cp_commit();
    }

    float* Zb = g_Z + (size_t)idx * TT * DD;
    #pragma unroll
    for (int mi = 0; mi < 2; ++mi) {
        #pragma unroll
        for (int rr = 0; rr < 2; ++rr) {
            int mloc = wm * 32 + mi * 16 + g + rr * 8;
            int m = m0 + mloc;
            if (m >= Nt) continue;
            int tk = stok[mloc];
            const float* xr = x + (size_t)tk * DD + n0 + wn * 32;
            float* zrow = Zb + (size_t)m * DD + n0 + wn * 32;
            #pragma unroll
            for (int ni = 0; ni < 4; ++ni) {
                #pragma unroll
                for (int cc = 0; cc < 2; ++cc) {
                    int col = ni * 8 + 2 * tig + cc;
                    zrow[col] = acc[mi][ni][rr * 2 + cc] + xr[col];
                }
            }
        }
    }
}

// fused: expert LN + expert combine + cluster LN + gate sum
__global__ void final_kernel(const float* __restrict__ loutg, const float* __restrict__ loutb,
                             const float* __restrict__ clng, const float* __restrict__ clnb,
                             float* __restrict__ out)
{
    int t = blockIdx.x;
    int tid = threadIdx.x;                    // 256
    __shared__ float rbuf[18];
    float o[4] = {};
    #pragma unroll
    for (int sI = 0; sI < 2; sI++) {
        float vcmb[4] = {};
        #pragma unroll
        for (int q = 0; q < 2; q++) {
            int slot = g_islot[t * 4 + sI * 2 + q];
            int pos  = g_ipos [t * 4 + sI * 2 + q];
            float cf = g_icoef[t * 4 + sI * 2 + q];
            const float* y = g_Z + ((size_t)slot * TT + pos) * DD;
            const float* gp = loutg + (size_t)slot * DD;
            const float* bp = loutb + (size_t)slot * DD;
            float v[4], s = 0.f, s2 = 0.f;
            #pragma unroll
            for (int r = 0; r < 4; r++) {
                int d = tid + 256 * r;
                v[r] = y[d]; s += v[r]; s2 += v[r] * v[r];
            }
            float mu, rs;
            block_meanvar_256(s, s2, rbuf, mu, rs);
            #pragma unroll
            for (int r = 0; r < 4; r++) {
                int d = tid + 256 * r;
                vcmb[r] += cf * ((v[r] - mu) * rs * gp[d] + bp[d]);
            }
        }
        float s = 0.f, s2 = 0.f;
        #pragma unroll
        for (int r = 0; r < 4; r++) { s += vcmb[r]; s2 += vcmb[r] * vcmb[r]; }
        float mu, rs;
        block_meanvar_256(s, s2, rbuf, mu, rs);
        int cc = g_sel[t * 2 + sI];
        float gt = g_gate[t * 2 + sI];
        #pragma unroll
        for (int r = 0; r < 4; r++) {
            int d = tid + 256 * r;
            o[r] += gt * ((vcmb[r] - mu) * rs * clng[cc * DD + d] + clnb[cc * DD + d]);
        }
    }
    #pragma unroll
    for (int r = 0; r < 4; r++)
        out[(size_t)t * DD + tid + 256 * r] = o[r];
}

// ---------------- launcher ----------------
extern "C" void kernel_launch(void* const* d_in, const int* in_sizes, int n_in,
                              void* d_out, int out_size)
{
    const float* x     = (const float*)d_in[0];
    const float* W1    = (const float*)d_in[1];
    const float* W2    = (const float*)d_in[2];
    const float* W3    = (const float*)d_in[3];
    const float* ling  = (const float*)d_in[4];
    const float* linb  = (const float*)d_in[5];
    const float* loutg = (const float*)d_in[6];
    const float* loutb = (const float*)d_in[7];
    const float* clng  = (const float*)d_in[8];
    const float* clnb  = (const float*)d_in[9];
    const float* Wrc   = (const float*)d_in[10];
    const float* brc   = (const float*)d_in[11];
    const float* Wre   = (const float*)d_in[12];
    const float* bre   = (const float*)d_in[13];
    float* out = (float*)d_out;

    // Detect whether the tcgen05 path was really compiled (arch-specific pass):
    // empty stub bodies compile to very few registers.
    cudaFuncAttributes fa{};
    cudaFuncGetAttributes(&fa, gemm1_tc_kernel<true, 2>);
    bool use_tc = (fa.numRegs >= 24);

    zero_cnt_kernel<<<1, 32>>>();
    routing_kernel<<<TT, 128>>>(x, Wrc, brc, Wre, bre);

    dim3 gp(TT, NEXP);
    prep_kernel<<<gp, 256>>>(x, ling, linb);

    if (use_tc) {
        float* w1t; cudaGetSymbolAddress((void**)&w1t, g_W1t);
        float* w2t; cudaGetSymbolAddress((void**)&w2t, g_W2t);
        float* w3t; cudaGetSymbolAddress((void**)&w3t, g_W3t);

        const int SM_TC_DUAL = 2 * (128*128 + 2*256*128) + 1024;   // 161KB
        const int SM_TC_SNGL = 3 * (128*128 +   256*128) + 1024;   // 145KB
        cudaFuncSetAttribute(gemm1_tc_kernel<true, 2>,
                             cudaFuncAttributeMaxDynamicSharedMemorySize, SM_TC_DUAL);
        cudaFuncSetAttribute(gemm1_tc_kernel<false, 3>,
                             cudaFuncAttributeMaxDynamicSharedMemorySize, SM_TC_SNGL);
        cudaFuncSetAttribute(gemm2_tc_kernel<3>,
                             cudaFuncAttributeMaxDynamicSharedMemorySize, SM_TC_SNGL);

        transpose_kernel<<<dim3(FF/32, DD/32, 16), 256>>>(W1, w1t, DD, FF, 0);
        transpose_kernel<<<dim3(FF/32, DD/32, 8),  256>>>(W2, w2t, DD, FF, 1);
        transpose_kernel<<<dim3(DD/32, FF/32, 16), 256>>>(W3, w3t, FF, DD, 0);

        dim3 g1(FF/256, TT/128, 8);
        gemm1_tc_kernel<true, 2><<<g1, 512, SM_TC_DUAL>>>(w1t, w2t);
        gemm1_tc_kernel<false, 3><<<g1, 512, SM_TC_SNGL>>>(w1t, w2t);

        dim3 g2(DD/256, TT/128, NEXP);
        gemm2_tc_kernel<3><<<g2, 512, SM_TC_SNGL>>>(x, w3t);
    } else {
        const int SM_DUAL = (NST * BM1 * APAD + 2 * NST * BKK * BPAD) * 4;
        const int SM_SNGL = (NST * BM1 * APAD +     NST * BKK * BPAD) * 4;
        cudaFuncSetAttribute(gemm1_mma_kernel<true>,
                             cudaFuncAttributeMaxDynamicSharedMemorySize, SM_DUAL);
        cudaFuncSetAttribute(gemm1_mma_kernel<false>,
                             cudaFuncAttributeMaxDynamicSharedMemorySize, SM_SNGL);
        cudaFuncSetAttribute(gemm2_mma_kernel,
                             cudaFuncAttributeMaxDynamicSharedMemorySize, SM_SNGL);

        dim3 g1(FF / BN1, TT / BM1, 8);
        gemm1_mma_kernel<true ><<<g1, NTH, SM_DUAL>>>(W1, W2);
        gemm1_mma_kernel<false><<<g1, NTH, SM_SNGL>>>(W1, W2);

        dim3 g2(DD / BN1, TT / BM1, NEXP);
        gemm2_mma_kernel<<<g2, NTH, SM_SNGL>>>(x, W3);
    }

    final_kernel<<<TT, 256>>>(loutg, loutb, clng, clnb, out);
}

// round 8
// speedup vs baseline: 1.0257x; 1.0003x over previous
#include <cuda_runtime.h>
#include <math.h>
#include <stdint.h>

#define TT 2048
#define DD 1024
#define FF 2048
#define CC 4
#define EE 4
#define NEXP 16
#define EPSL 1e-5f

#if defined(__CUDA_ARCH_FEAT_SM103_ALL) || defined(__CUDA_ARCH_FEAT_SM100_ALL) || \
    (defined(__CUDA_ARCH_SPECIFIC__) && (__CUDA_ARCH_SPECIFIC__ >= 1000))
#define TC_OK 1
#else
#define TC_OK 0
#endif

// ---------------- device scratch ----------------
__device__ float g_A[16ULL*2048ULL*1024ULL];
__device__ float g_H[16ULL*2048ULL*2048ULL];
__device__ float g_Z[16ULL*2048ULL*1024ULL];
__device__ float g_W1t[16ULL*2048ULL*1024ULL]; // [idx][F][D]
__device__ float g_W2t[16ULL*2048ULL*1024ULL]; // [idx][F][D]
__device__ float g_W3t[16ULL*1024ULL*2048ULL]; // [idx][D][F]
__device__ int   g_cnt[NEXP];
__device__ int   g_tok[NEXP*TT];
__device__ float g_mu[TT];
__device__ float g_rstd[TT];
__device__ int   g_sel[TT*2];
__device__ float g_gate[TT*2];
__device__ int   g_islot[TT*4];
__device__ int   g_ipos[TT*4];
__device__ float g_icoef[TT*4];

// ---------------- helpers ----------------
__device__ __forceinline__ float tf32r(float f) {
    uint32_t r;
    asm("cvt.rna.tf32.f32 %0, %1;" : "=r"(r) : "f"(f));
    return __uint_as_float(r);
}
__device__ __forceinline__ void cp16(uint32_t dst, const void* src) {
    asm volatile("cp.async.cg.shared.global [%0], [%1], 16;\n" :: "r"(dst), "l"(src));
}
__device__ __forceinline__ void cp_commit() {
    asm volatile("cp.async.commit_group;\n" ::: "memory");
}
template<int N>
__device__ __forceinline__ void cp_waitn() {
    asm volatile("cp.async.wait_group %0;\n" :: "n"(N) : "memory");
}
__device__ __forceinline__ uint32_t smem_u32(const void* p) {
    uint32_t a;
    asm("{ .reg .u64 t; cvta.to.shared.u64 t, %1; cvt.u32.u64 %0, t; }" : "=r"(a) : "l"(p));
    return a;
}
#define SWZ128(off) ((off) ^ (((off) >> 3) & 0x70))

__device__ __forceinline__ void block_meanvar_256(float s, float s2, float* rbuf,
                                                  float& mu, float& rs)
{
    int tid = threadIdx.x, lane = tid & 31, w = tid >> 5;
    __syncthreads();
    #pragma unroll
    for (int o = 16; o; o >>= 1) {
        s  += __shfl_down_sync(0xffffffffu, s,  o);
        s2 += __shfl_down_sync(0xffffffffu, s2, o);
    }
    if (lane == 0) { rbuf[w] = s; rbuf[8 + w] = s2; }
    __syncthreads();
    if (tid == 0) {
        float S = 0.f, S2 = 0.f;
        #pragma unroll
        for (int ww = 0; ww < 8; ww++) { S += rbuf[ww]; S2 += rbuf[8 + ww]; }
        float m = S / (float)DD;
        rbuf[16] = m;
        rbuf[17] = rsqrtf(S2 / (float)DD - m * m + EPSL);
    }
    __syncthreads();
    mu = rbuf[16];
    rs = rbuf[17];
}

// ---------------- small kernels ----------------
__global__ void zero_cnt_kernel()
{
    if (threadIdx.x < NEXP) g_cnt[threadIdx.x] = 0;
}

__global__ void routing_kernel(const float* __restrict__ x,
                               const float* __restrict__ Wrc, const float* __restrict__ brc,
                               const float* __restrict__ Wre, const float* __restrict__ bre)
{
    int t = blockIdx.x;
    __shared__ float xs[DD];
    __shared__ float rbuf[16];
    __shared__ float lgs[20];
    int tid = threadIdx.x;          // 128
    int lane = tid & 31, wid = tid >> 5;

    float s = 0.f, s2 = 0.f;
    for (int d = tid; d < DD; d += 128) {
        float v = x[(size_t)t * DD + d];
        xs[d] = v; s += v; s2 += v * v;
    }
    #pragma unroll
    for (int o = 16; o; o >>= 1) {
        s  += __shfl_down_sync(0xffffffffu, s,  o);
        s2 += __shfl_down_sync(0xffffffffu, s2, o);
    }
    if (lane == 0) { rbuf[wid] = s; rbuf[8 + wid] = s2; }
    __syncthreads();
    if (tid == 0) {
        float S  = rbuf[0] + rbuf[1] + rbuf[2] + rbuf[3];
        float S2 = rbuf[8] + rbuf[9] + rbuf[10] + rbuf[11];
        float mu = S / (float)DD;
        g_mu[t] = mu;
        g_rstd[t] = rsqrtf(S2 / (float)DD - mu * mu + EPSL);
    }

    for (int v = wid; v < 20; v += 4) {
        float acc = 0.f;
        if (v < CC) {
            for (int d = lane; d < DD; d += 32) acc += xs[d] * Wrc[d * CC + v];
        } else {
            int cc = (v - 4) >> 2, e = (v - 4) & 3;
            const float* wp = Wre + (size_t)cc * DD * EE + e;
            for (int d = lane; d < DD; d += 32) acc += xs[d] * wp[d * EE];
        }
        #pragma unroll
        for (int o = 16; o; o >>= 1) acc += __shfl_down_sync(0xffffffffu, acc, o);
        if (lane == 0) lgs[v] = acc;
    }
    __syncthreads();

    if (tid == 0) {
        float p[CC];
        float mx = -1e30f;
        for (int c = 0; c < CC; c++) { p[c] = lgs[c] + brc[c]; mx = fmaxf(mx, p[c]); }
        float ss = 0.f;
        for (int c = 0; c < CC; c++) { p[c] = expf(p[c] - mx); ss += p[c]; }
        for (int c = 0; c < CC; c++) p[c] /= ss;
        int i0 = 0;
        for (int c = 1; c < CC; c++) if (p[c] > p[i0]) i0 = c;
        int i1 = -1;
        for (int c = 0; c < CC; c++) if (c != i0 && (i1 < 0 || p[c] > p[i1])) i1 = c;
        float swt = p[i0] + p[i1];
        int sel[2] = { i0, i1 };
        float gv[2] = { p[i0] / swt, p[i1] / swt };

        for (int sI = 0; sI < 2; sI++) {
            int cc = sel[sI];
            g_sel[t * 2 + sI]  = cc;
            g_gate[t * 2 + sI] = gv[sI];
            float el[EE];
            for (int e = 0; e < EE; e++) el[e] = lgs[4 + cc * 4 + e] + bre[cc * EE + e];
            int e0 = 0;
            for (int e = 1; e < EE; e++) if (el[e] > el[e0]) e0 = e;
            int e1 = -1;
            for (int e = 0; e < EE; e++) if (e != e0 && (e1 < 0 || el[e] > el[e1])) e1 = e;
            float z = expf(el[e1] - el[e0]);
            float w0 = 1.f / (1.f + z), w1 = z / (1.f + z);
            int   eS[2] = { e0, e1 };
            float wS[2] = { w0, w1 };
            for (int q = 0; q < 2; q++) {
                int slot = cc * EE + eS[q];
                int pos = atomicAdd(&g_cnt[slot], 1);
                g_tok[slot * TT + pos] = t;
                g_islot[t * 4 + sI * 2 + q] = slot;
                g_ipos [t * 4 + sI * 2 + q] = pos;
                g_icoef[t * 4 + sI * 2 + q] = wS[q];
            }
        }
    }
}

__global__ void prep_kernel(const float* __restrict__ x,
                            const float* __restrict__ ling, const float* __restrict__ linb)
{
    int idx = blockIdx.y;
    int i = blockIdx.x;
    if (i >= g_cnt[idx]) return;
    int tok = g_tok[idx * TT + i];
    float mu = g_mu[tok], rs = g_rstd[tok];
    const float4* xr = (const float4*)(x + (size_t)tok * DD);
    const float4* gp = (const float4*)(ling + (size_t)idx * DD);
    const float4* bp = (const float4*)(linb + (size_t)idx * DD);
    float4* ar = (float4*)(g_A + ((size_t)idx * TT + i) * DD);
    int d = threadIdx.x;
    float4 xv = xr[d], gv = gp[d], bv = bp[d];
    float4 o;
    o.x = tf32r((xv.x - mu) * rs * gv.x + bv.x);
    o.y = tf32r((xv.y - mu) * rs * gv.y + bv.y);
    o.z = tf32r((xv.z - mu) * rs * gv.z + bv.z);
    o.w = tf32r((xv.w - mu) * rs * gv.w + bv.w);
    ar[d] = o;
}

__global__ void transpose_kernel(const float* __restrict__ in, float* __restrict__ out,
                                 int R, int C, int dualmap)
{
    __shared__ float t[32][33];
    int z = blockIdx.z;
    int idx = dualmap ? ((z >> 1) * 4 + ((z & 1) ? 3 : 0)) : z;
    const float* ip = in + (size_t)idx * R * C;
    float* op = out + (size_t)idx * R * C;
    int c0 = blockIdx.x * 32, r0 = blockIdx.y * 32;
    int tx = threadIdx.x & 31, ty = threadIdx.x >> 5;
    #pragma unroll
    for (int i = 0; i < 4; i++)
        t[ty + 8 * i][tx] = tf32r(ip[(size_t)(r0 + ty + 8 * i) * C + c0 + tx]);
    __syncthreads();
    #pragma unroll
    for (int i = 0; i < 4; i++)
        op[(size_t)(c0 + ty + 8 * i) * R + r0 + tx] = t[tx][ty + 8 * i];
}

// ================= tcgen05 machinery =================
#if TC_OK
static constexpr uint64_t SMEM_DESC_BASE_SW128 =
    (uint64_t(2)  << 61) | (uint64_t(1) << 46) | (uint64_t(64) << 32) | (uint64_t(1) << 16);
#define MAKE_SMEM_DESC(base_addr) \
    (SMEM_DESC_BASE_SW128 | ((uint64_t)((base_addr) >> 4) & 0x3FFF))
#define IDESC_TF32_N128 ((1u<<4) | (2u<<7) | (2u<<10) | ((128u/8u)<<17) | ((128u/16u)<<24))

__device__ __forceinline__ void umma_tf32(uint32_t d_tmem, uint64_t a_desc,
                                          uint64_t b_desc, uint32_t idesc, uint32_t en)
{
    asm volatile(
        "{\n\t.reg .pred p;\n\t"
        "setp.ne.u32 p, %5, 0;\n\t"
        "tcgen05.mma.cta_group::1.kind::tf32 [%0], %1, %2, %3, {%4, %4, %4, %4}, p;\n\t"
        "}"
        :: "r"(d_tmem), "l"(a_desc), "l"(b_desc), "r"(idesc), "r"(0u), "r"(en)
        : "memory");
}
__device__ __forceinline__ uint32_t elect_one_pred() {
    uint32_t pred;
    asm volatile(
        "{\n\t.reg .pred p;\n\telect.sync _|p, 0xFFFFFFFF;\n\tselp.b32 %0, 1, 0, p;\n\t}"
        : "=r"(pred));
    return pred;
}
__device__ __forceinline__ void fence_proxy_async() {
    asm volatile("fence.proxy.async;" ::: "memory");
}
#define TCGEN05_ALLOC(sa, n) \
    asm volatile("tcgen05.alloc.cta_group::1.sync.aligned.shared::cta.b32 [%0], %1;" \
        :: "r"((uint32_t)(sa)), "r"((uint32_t)(n)) : "memory")
#define TCGEN05_DEALLOC(t, n) \
    asm volatile("tcgen05.dealloc.cta_group::1.sync.aligned.b32 %0, %1;" \
        :: "r"(t), "r"((uint32_t)(n)))
#define TCGEN05_RELINQUISH() \
    asm volatile("tcgen05.relinquish_alloc_permit.cta_group::1.sync.aligned;")
#define TCGEN05_COMMIT(mb) \
    asm volatile("tcgen05.commit.cta_group::1.mbarrier::arrive::one.shared::cluster.b64 [%0];" \
        :: "r"((uint32_t)(mb)) : "memory")
#define TCGEN05_FENCE_AFTER() \
    asm volatile("tcgen05.fence::after_thread_sync;" ::: "memory")
#define TCGEN05_WAIT_LD() \
    asm volatile("tcgen05.wait::ld.sync.aligned;" ::: "memory")
#define TCGEN05_LD_X16(r, ta) \
    asm volatile( \
        "tcgen05.ld.sync.aligned.32x32b.x16.b32 " \
        "{%0, %1, %2, %3, %4, %5, %6, %7, " \
        " %8, %9, %10, %11, %12, %13, %14, %15}, [%16];" \
        : "=r"((r)[0]),  "=r"((r)[1]),  "=r"((r)[2]),  "=r"((r)[3]), \
          "=r"((r)[4]),  "=r"((r)[5]),  "=r"((r)[6]),  "=r"((r)[7]), \
          "=r"((r)[8]),  "=r"((r)[9]),  "=r"((r)[10]), "=r"((r)[11]), \
          "=r"((r)[12]), "=r"((r)[13]), "=r"((r)[14]), "=r"((r)[15]) \
        : "r"(ta))
#define MBARRIER_INIT(mb, c) \
    asm volatile("mbarrier.init.shared.b64 [%0], %1;" \
        :: "r"((uint32_t)(mb)), "r"((uint32_t)(c)) : "memory")
#define MBARRIER_INVAL(mb) \
    asm volatile("mbarrier.inval.shared.b64 [%0];" :: "r"((uint32_t)(mb)) : "memory")
#define MBAR_WAIT(mb, parity) do { \
    uint32_t _m = (uint32_t)(mb); \
    uint32_t _p = (uint32_t)(parity); \
    uint32_t _done; \
    asm volatile( \
        "{\n\t.reg .pred p;\n\t" \
        "mbarrier.try_wait.parity.acquire.cta.shared::cta.b64 p, [%1], %2;\n\t" \
        "selp.b32 %0, 1, 0, p;\n\t}" \
        : "=r"(_done) : "r"(_m), "r"(_p) : "memory"); \
    if (!_done) { \
        asm volatile( \
            "{\n\t.reg .pred P1;\n\t" \
            "WAIT_LOOP_%=:\n\t" \
            "mbarrier.try_wait.parity.acquire.cta.shared::cta.b64 P1, [%0], %1, 0x989680;\n\t" \
            "@P1 bra.uni WAIT_DONE_%=;\n\t" \
            "bra.uni WAIT_LOOP_%=;\n\t" \
            "WAIT_DONE_%=:\n\t}" \
            :: "r"(_m), "r"(_p) : "memory"); \
    } \
} while (0)
#endif

#define NSTG 3
#define ASZ 32768u   // 2 m-blocks x 128 rows x 128B
#define BSZ 32768u   // 256 rows x 128B
#define SMEM_TC (NSTG * (ASZ + BSZ) + 1024)

// GEMM1: H = act(A @ W^T). Per CTA: 2 m-blocks of 128 rows, 256 B-rows streamed.
// DUAL: B rows = [W1 slice(128 f-cols); W2 slice(same f-cols)], output 128 f-cols.
// !DUAL: B rows = 256 f-cols of W1.
template<bool DUAL>
__global__ void __launch_bounds__(512, 1)
gemm1_tc_kernel(const float* __restrict__ W1t, const float* __restrict__ W2t)
{
#if TC_OK
    int z = blockIdx.z;
    int idx = DUAL ? ((z >> 1) * 4 + ((z & 1) ? 3 : 0))
                   : ((z >> 1) * 4 + ((z & 1) ? 2 : 1));
    int Nt = g_cnt[idx];
    int m0 = blockIdx.y * 256;
    if (m0 >= Nt) return;
    const int NCOLS = DUAL ? 128 : 256;
    int n0 = blockIdx.x * NCOLS;
    const float* Ab  = g_A  + (size_t)idx * TT * DD;
    const float* B1g = W1t + (size_t)idx * DD * FF;
    const float* B2g = W2t + (size_t)idx * DD * FF;

    extern __shared__ __align__(1024) char smem[];
    uint32_t sb = smem_u32(smem);
    uint32_t aBase = sb;
    uint32_t bBase = sb + NSTG * ASZ;
    uint32_t ctrl  = bBase + NSTG * BSZ;

    int tid = threadIdx.x;
    int w = tid >> 5;

    if (w == 0) TCGEN05_ALLOC(ctrl, 512);
    if (tid == 0) MBARRIER_INIT(ctrl + 8, 1);
    __syncthreads();
    uint32_t tmem;
    asm volatile("ld.shared.b32 %0, [%1];" : "=r"(tmem) : "r"(ctrl));

    auto load_chunk = [&](int st, int ch) {
        int k0 = ch * 32;
        #pragma unroll
        for (int i = 0; i < 4; ++i) {               // A: 256 rows
            int lin = tid + 512 * i;
            int row = lin >> 3, c16 = lin & 7;
            uint32_t off = (uint32_t)((row & 127) * 128 + c16 * 16);
            cp16(aBase + st * ASZ + (uint32_t)(row >> 7) * 16384u + SWZ128(off),
                 Ab + (size_t)(m0 + row) * DD + k0 + c16 * 4);
        }
        #pragma unroll
        for (int i = 0; i < 4; ++i) {               // B: 256 rows
            int lin = tid + 512 * i;
            int row = lin >> 3, c16 = lin & 7;
            uint32_t off = (uint32_t)((row & 127) * 128 + c16 * 16);
            const float* src;
            if (DUAL) src = (row < 128) ? (B1g + (size_t)(n0 + row) * DD)
                                        : (B2g + (size_t)(n0 + row - 128) * DD);
            else      src = B1g + (size_t)(n0 + row) * DD;
            cp16(bBase + st * BSZ + (uint32_t)(row >> 7) * 16384u + SWZ128(off),
                 src + k0 + c16 * 4);
        }
    };

    const int NCH = DD / 32;   // 32
    load_chunk(0, 0); cp_commit();
    load_chunk(1, 1); cp_commit();

    for (int it = 0; it < NCH; ++it) {
        int buf = it % NSTG;
        cp_waitn<NSTG - 2>();
        __syncthreads();
        if (w == 0 && elect_one_pred()) {
            fence_proxy_async();
            #pragma unroll
            for (int m = 0; m < 2; ++m) {
                uint64_t ad = MAKE_SMEM_DESC(aBase + buf * ASZ + m * 16384u);
                #pragma unroll
                for (int half = 0; half < 2; ++half) {
                    uint64_t bd = MAKE_SMEM_DESC(bBase + buf * BSZ + half * 16384u);
                    #pragma unroll
                    for (int k = 0; k < 4; ++k)
                        umma_tf32(tmem + m * 256 + half * 128, ad + 2 * k, bd + 2 * k,
                                  IDESC_TF32_N128, (uint32_t)(it > 0 || k > 0));
                }
            }
            TCGEN05_COMMIT(ctrl + 8);
        }
        if (it >= 1) MBAR_WAIT(ctrl + 8, (it - 1) & 1);
        if (it + NSTG - 1 < NCH) load_chunk((it + NSTG - 1) % NSTG, it + NSTG - 1);
        cp_commit();
    }
    MBAR_WAIT(ctrl + 8, (NCH - 1) & 1);
    TCGEN05_FENCE_AFTER();

    int lane = tid & 31;
    int sub = w & 3, grp = w >> 2;
    int act = (idx & 3) % 3;
    float* Hb = g_H + (size_t)idx * TT * FF;
    #pragma unroll
    for (int mblk = 0; mblk < 2; ++mblk) {
        int mrow = m0 + mblk * 128 + sub * 32 + lane;
        bool valid = mrow < Nt;
        uint32_t tb = tmem + mblk * 256;
        if (DUAL) {
            #pragma unroll
            for (int cc = 0; cc < 2; ++cc) {
                uint32_t d1[16], d2[16];
                TCGEN05_LD_X16(d1, tb + grp * 32 + cc * 16);
                TCGEN05_LD_X16(d2, tb + 128 + grp * 32 + cc * 16);
                TCGEN05_WAIT_LD();
                if (valid) {
                    float h[16];
                    #pragma unroll
                    for (int r = 0; r < 16; ++r) {
                        float h1 = __uint_as_float(d1[r]);
                        float h2 = __uint_as_float(d2[r]);
                        float sg = 1.f / (1.f + expf(-h2));
                        h[r] = tf32r(h2 * sg * h2 * h1);
                    }
                    float4* p = (float4*)(Hb + (size_t)mrow * FF + n0 + grp * 32 + cc * 16);
                    #pragma unroll
                    for (int v = 0; v < 4; ++v)
                        p[v] = make_float4(h[4*v], h[4*v+1], h[4*v+2], h[4*v+3]);
                }
            }
        } else {
            #pragma unroll
            for (int cc = 0; cc < 4; ++cc) {
                uint32_t d1[16];
                TCGEN05_LD_X16(d1, tb + grp * 64 + cc * 16);
                TCGEN05_WAIT_LD();
                if (valid) {
                    float h[16];
                    #pragma unroll
                    for (int r = 0; r < 16; ++r) {
                        float h1 = __uint_as_float(d1[r]);
                        float hv = (act == 1)
                            ? 0.5f * h1 * (1.f + erff(h1 * 0.70710678118654752f))
                            : fmaxf(h1, 0.f);
                        h[r] = tf32r(hv);
                    }
                    float4* p = (float4*)(Hb + (size_t)mrow * FF + n0 + grp * 64 + cc * 16);
                    #pragma unroll
                    for (int v = 0; v < 4; ++v)
                        p[v] = make_float4(h[4*v], h[4*v+1], h[4*v+2], h[4*v+3]);
                }
            }
        }
    }
    __syncthreads();
    if (tid == 0) MBARRIER_INVAL(ctrl + 8);
    if (w == 0) { TCGEN05_RELINQUISH(); TCGEN05_DEALLOC(tmem, 512); }
#endif
}

// GEMM2: Z = x + H @ W3t^T. Per CTA: 2 m-blocks x 256 n-cols, K=FF.
__global__ void __launch_bounds__(512, 1)
gemm2_tc_kernel(const float* __restrict__ x, const float* __restrict__ W3t)
{
#if TC_OK
    int idx = blockIdx.z;
    int Nt = g_cnt[idx];
    int m0 = blockIdx.y * 256;
    if (m0 >= Nt) return;
    int n0 = blockIdx.x * 256;
    const float* Ab = g_H  + (size_t)idx * TT * FF;
    const float* Bg = W3t + (size_t)idx * DD * FF;

    extern __shared__ __align__(1024) char smem[];
    uint32_t sb = smem_u32(smem);
    uint32_t aBase = sb;
    uint32_t bBase = sb + NSTG * ASZ;
    uint32_t ctrl  = bBase + NSTG * BSZ;

    int tid = threadIdx.x;
    int w = tid >> 5;

    if (w == 0) TCGEN05_ALLOC(ctrl, 512);
    if (tid == 0) MBARRIER_INIT(ctrl + 8, 1);
    __syncthreads();
    uint32_t tmem;
    asm volatile("ld.shared.b32 %0, [%1];" : "=r"(tmem) : "r"(ctrl));

    auto load_chunk = [&](int st, int ch) {
        int k0 = ch * 32;
        #pragma unroll
        for (int i = 0; i < 4; ++i) {
            int lin = tid + 512 * i;
            int row = lin >> 3, c16 = lin & 7;
            uint32_t off = (uint32_t)((row & 127) * 128 + c16 * 16);
            cp16(aBase + st * ASZ + (uint32_t)(row >> 7) * 16384u + SWZ128(off),
                 Ab + (size_t)(m0 + row) * FF + k0 + c16 * 4);
        }
        #pragma unroll
        for (int i = 0; i < 4; ++i) {
            int lin = tid + 512 * i;
            int row = lin >> 3, c16 = lin & 7;
            uint32_t off = (uint32_t)((row & 127) * 128 + c16 * 16);
            cp16(bBase + st * BSZ + (uint32_t)(row >> 7) * 16384u + SWZ128(off),
                 Bg + (size_t)(n0 + row) * FF + k0 + c16 * 4);
        }
    };

    const int NCH = FF / 32;   // 64
    load_chunk(0, 0); cp_commit();
    load_chunk(1, 1); cp_commit();

    for (int it = 0; it < NCH; ++it) {
        int buf = it % NSTG;
        cp_waitn<NSTG - 2>();
        __syncthreads();
        if (w == 0 && elect_one_pred()) {
            fence_proxy_async();
            #pragma unroll
            for (int m = 0; m < 2; ++m) {
                uint64_t ad = MAKE_SMEM_DESC(aBase + buf * ASZ + m * 16384u);
                #pragma unroll
                for (int half = 0; half < 2; ++half) {
                    uint64_t bd = MAKE_SMEM_DESC(bBase + buf * BSZ + half * 16384u);
                    #pragma unroll
                    for (int k = 0; k < 4; ++k)
                        umma_tf32(tmem + m * 256 + half * 128, ad + 2 * k, bd + 2 * k,
                                  IDESC_TF32_N128, (uint32_t)(it > 0 || k > 0));
                }
            }
            TCGEN05_COMMIT(ctrl + 8);
        }
        if (it >= 1) MBAR_WAIT(ctrl + 8, (it - 1) & 1);
        if (it + NSTG - 1 < NCH) load_chunk((it + NSTG - 1) % NSTG, it + NSTG - 1);
        cp_commit();
    }
    MBAR_WAIT(ctrl + 8, (NCH - 1) & 1);
    TCGEN05_FENCE_AFTER();

    int lane = tid & 31;
    int sub = w & 3, grp = w >> 2;
    float* Zb = g_Z + (size_t)idx * TT * DD;
    #pragma unroll
    for (int mblk = 0; mblk < 2; ++mblk) {
        int mrow = m0 + mblk * 128 + sub * 32 + lane;
        bool valid = mrow < Nt;
        int tok = valid ? g_tok[idx * TT + mrow] : 0;
        uint32_t tb = tmem + mblk * 256;
        #pragma unroll
        for (int cc = 0; cc < 4; ++cc) {
            uint32_t d1[16];
            TCGEN05_LD_X16(d1, tb + grp * 64 + cc * 16);
            TCGEN05_WAIT_LD();
            if (valid) {
                const float4* xr = (const float4*)(x + (size_t)tok * DD + n0 + grp * 64 + cc * 16);
                float4* p = (float4*)(Zb + (size_t)mrow * DD + n0 + grp * 64 + cc * 16);
                #pragma unroll
                for (int v = 0; v < 4; ++v) {
                    float4 xv = xr[v];
                    p[v] = make_float4(__uint_as_float(d1[4*v])   + xv.x,
                                       __uint_as_float(d1[4*v+1]) + xv.y,
                                       __uint_as_float(d1[4*v+2]) + xv.z,
                                       __uint_as_float(d1[4*v+3]) + xv.w);
                }
            }
        }
    }
    __syncthreads();
    if (tid == 0) MBARRIER_INVAL(ctrl + 8);
    if (w == 0) { TCGEN05_RELINQUISH(); TCGEN05_DEALLOC(tmem, 512); }
#endif
}

// fused: expert LN + expert combine + cluster LN + gate sum
__global__ void final_kernel(const float* __restrict__ loutg, const float* __restrict__ loutb,
                             const float* __restrict__ clng, const float* __restrict__ clnb,
                             float* __restrict__ out)
{
    int t = blockIdx.x;
    int tid = threadIdx.x;                    // 256
    __shared__ float rbuf[18];
    float o[4] = {};
    #pragma unroll
    for (int sI = 0; sI < 2; sI++) {
        float vcmb[4] = {};
        #pragma unroll
        for (int q = 0; q < 2; q++) {
            int slot = g_islot[t * 4 + sI * 2 + q];
            int pos  = g_ipos [t * 4 + sI * 2 + q];
            float cf = g_icoef[t * 4 + sI * 2 + q];
            const float* y = g_Z + ((size_t)slot * TT + pos) * DD;
            const float* gp = loutg + (size_t)slot * DD;
            const float* bp = loutb + (size_t)slot * DD;
            float v[4], s = 0.f, s2 = 0.f;
            #pragma unroll
            for (int r = 0; r < 4; r++) {
                int d = tid + 256 * r;
                v[r] = y[d]; s += v[r]; s2 += v[r] * v[r];
            }
            float mu, rs;
            block_meanvar_256(s, s2, rbuf, mu, rs);
            #pragma unroll
            for (int r = 0; r < 4; r++) {
                int d = tid + 256 * r;
                vcmb[r] += cf * ((v[r] - mu) * rs * gp[d] + bp[d]);
            }
        }
        float s = 0.f, s2 = 0.f;
        #pragma unroll
        for (int r = 0; r < 4; r++) { s += vcmb[r]; s2 += vcmb[r] * vcmb[r]; }
        float mu, rs;
        block_meanvar_256(s, s2, rbuf, mu, rs);
        int cc = g_sel[t * 2 + sI];
        float gt = g_gate[t * 2 + sI];
        #pragma unroll
        for (int r = 0; r < 4; r++) {
            int d = tid + 256 * r;
            o[r] += gt * ((vcmb[r] - mu) * rs * clng[cc * DD + d] + clnb[cc * DD + d]);
        }
    }
    #pragma unroll
    for (int r = 0; r < 4; r++)
        out[(size_t)t * DD + tid + 256 * r] = o[r];
}

// ---------------- launcher ----------------
extern "C" void kernel_launch(void* const* d_in, const int* in_sizes, int n_in,
                              void* d_out, int out_size)
{
    const float* x     = (const float*)d_in[0];
    const float* W1    = (const float*)d_in[1];
    const float* W2    = (const float*)d_in[2];
    const float* W3    = (const float*)d_in[3];
    const float* ling  = (const float*)d_in[4];
    const float* linb  = (const float*)d_in[5];
    const float* loutg = (const float*)d_in[6];
    const float* loutb = (const float*)d_in[7];
    const float* clng  = (const float*)d_in[8];
    const float* clnb  = (const float*)d_in[9];
    const float* Wrc   = (const float*)d_in[10];
    const float* brc   = (const float*)d_in[11];
    const float* Wre   = (const float*)d_in[12];
    const float* bre   = (const float*)d_in[13];
    float* out = (float*)d_out;

    float* w1t; cudaGetSymbolAddress((void**)&w1t, g_W1t);
    float* w2t; cudaGetSymbolAddress((void**)&w2t, g_W2t);
    float* w3t; cudaGetSymbolAddress((void**)&w3t, g_W3t);

    cudaFuncSetAttribute(gemm1_tc_kernel<true>,
                         cudaFuncAttributeMaxDynamicSharedMemorySize, SMEM_TC);
    cudaFuncSetAttribute(gemm1_tc_kernel<false>,
                         cudaFuncAttributeMaxDynamicSharedMemorySize, SMEM_TC);
    cudaFuncSetAttribute(gemm2_tc_kernel,
                         cudaFuncAttributeMaxDynamicSharedMemorySize, SMEM_TC);

    zero_cnt_kernel<<<1, 32>>>();
    routing_kernel<<<TT, 128>>>(x, Wrc, brc, Wre, bre);

    dim3 gp(TT, NEXP);
    prep_kernel<<<gp, 256>>>(x, ling, linb);

    transpose_kernel<<<dim3(FF/32, DD/32, 16), 256>>>(W1, w1t, DD, FF, 0);
    transpose_kernel<<<dim3(FF/32, DD/32, 8),  256>>>(W2, w2t, DD, FF, 1);
    transpose_kernel<<<dim3(DD/32, FF/32, 16), 256>>>(W3, w3t, FF, DD, 0);

    dim3 g1d(FF/128, TT/256, 8);
    gemm1_tc_kernel<true><<<g1d, 512, SMEM_TC>>>(w1t, w2t);
    dim3 g1s(FF/256, TT/256, 8);
    gemm1_tc_kernel<false><<<g1s, 512, SMEM_TC>>>(w1t, w2t);

    dim3 g2(DD/256, TT/256, NEXP);
    gemm2_tc_kernel<<<g2, 512, SMEM_TC>>>(x, w3t);

    final_kernel<<<TT, 256>>>(loutg, loutb, clng, clnb, out);
}

// round 9
// speedup vs baseline: 1.5012x; 1.4635x over previous
#include <cuda_runtime.h>
#include <math.h>
#include <stdint.h>

#define TT 2048
#define DD 1024
#define FF 2048
#define CC 4
#define EE 4
#define NEXP 16
#define EPSL 1e-5f

#if defined(__CUDA_ARCH_FEAT_SM103_ALL) || defined(__CUDA_ARCH_FEAT_SM100_ALL) || \
    (defined(__CUDA_ARCH_SPECIFIC__) && (__CUDA_ARCH_SPECIFIC__ >= 1000))
#define TC_OK 1
#else
#define TC_OK 0
#endif

// ---------------- device scratch (packed swizzled tile images) ----------------
// g_A  : [idx][ch(32)][mb(16)][4096 floats]   (LN'd input, tf32-rounded, SW128 image)
// g_H  : [idx][ch(64)][mb(16)][4096 floats]   (activated hidden, tf32-rounded, SW128 image)
// g_W1t: [idx][ch(32)][nb(16)][4096 floats]   (W1^T images)
// g_W2t: [idx][ch(32)][nb(16)][4096 floats]
// g_W3t: [idx][ch(64)][nb(8) ][4096 floats]
__device__ float g_A[16ULL*2048ULL*1024ULL];
__device__ float g_H[16ULL*2048ULL*2048ULL];
__device__ float g_Z[16ULL*2048ULL*1024ULL];
__device__ float g_W1t[16ULL*2048ULL*1024ULL];
__device__ float g_W2t[16ULL*2048ULL*1024ULL];
__device__ float g_W3t[16ULL*1024ULL*2048ULL];
__device__ int   g_cnt[NEXP];
__device__ int   g_tok[NEXP*TT];
__device__ float g_mu[TT];
__device__ float g_rstd[TT];
__device__ int   g_sel[TT*2];
__device__ float g_gate[TT*2];
__device__ int   g_islot[TT*4];
__device__ int   g_ipos[TT*4];
__device__ float g_icoef[TT*4];

// ---------------- helpers ----------------
__device__ __forceinline__ float tf32r(float f) {
    uint32_t r;
    asm("cvt.rna.tf32.f32 %0, %1;" : "=r"(r) : "f"(f));
    return __uint_as_float(r);
}
__device__ __forceinline__ uint32_t smem_u32(const void* p) {
    uint32_t a;
    asm("{ .reg .u64 t; cvta.to.shared.u64 t, %1; cvt.u32.u64 %0, t; }" : "=r"(a) : "l"(p));
    return a;
}
#define SWZ128(off) ((off) ^ (((off) >> 3) & 0x70))

__device__ __forceinline__ void block_meanvar_256(float s, float s2, float* rbuf,
                                                  float& mu, float& rs)
{
    int tid = threadIdx.x, lane = tid & 31, w = tid >> 5;
    __syncthreads();
    #pragma unroll
    for (int o = 16; o; o >>= 1) {
        s  += __shfl_down_sync(0xffffffffu, s,  o);
        s2 += __shfl_down_sync(0xffffffffu, s2, o);
    }
    if (lane == 0) { rbuf[w] = s; rbuf[8 + w] = s2; }
    __syncthreads();
    if (tid == 0) {
        float S = 0.f, S2 = 0.f;
        #pragma unroll
        for (int ww = 0; ww < 8; ww++) { S += rbuf[ww]; S2 += rbuf[8 + ww]; }
        float m = S / (float)DD;
        rbuf[16] = m;
        rbuf[17] = rsqrtf(S2 / (float)DD - m * m + EPSL);
    }
    __syncthreads();
    mu = rbuf[16];
    rs = rbuf[17];
}

// ---------------- small kernels ----------------
__global__ void zero_cnt_kernel()
{
    if (threadIdx.x < NEXP) g_cnt[threadIdx.x] = 0;
}

__global__ void routing_kernel(const float* __restrict__ x,
                               const float* __restrict__ Wrc, const float* __restrict__ brc,
                               const float* __restrict__ Wre, const float* __restrict__ bre)
{
    int t = blockIdx.x;
    __shared__ float xs[DD];
    __shared__ float rbuf[16];
    __shared__ float lgs[20];
    int tid = threadIdx.x;          // 128
    int lane = tid & 31, wid = tid >> 5;

    float s = 0.f, s2 = 0.f;
    for (int d = tid; d < DD; d += 128) {
        float v = x[(size_t)t * DD + d];
        xs[d] = v; s += v; s2 += v * v;
    }
    #pragma unroll
    for (int o = 16; o; o >>= 1) {
        s  += __shfl_down_sync(0xffffffffu, s,  o);
        s2 += __shfl_down_sync(0xffffffffu, s2, o);
    }
    if (lane == 0) { rbuf[wid] = s; rbuf[8 + wid] = s2; }
    __syncthreads();
    if (tid == 0) {
        float S  = rbuf[0] + rbuf[1] + rbuf[2] + rbuf[3];
        float S2 = rbuf[8] + rbuf[9] + rbuf[10] + rbuf[11];
        float mu = S / (float)DD;
        g_mu[t] = mu;
        g_rstd[t] = rsqrtf(S2 / (float)DD - mu * mu + EPSL);
    }

    for (int v = wid; v < 20; v += 4) {
        float acc = 0.f;
        if (v < CC) {
            for (int d = lane; d < DD; d += 32) acc += xs[d] * Wrc[d * CC + v];
        } else {
            int cc = (v - 4) >> 2, e = (v - 4) & 3;
            const float* wp = Wre + (size_t)cc * DD * EE + e;
            for (int d = lane; d < DD; d += 32) acc += xs[d] * wp[d * EE];
        }
        #pragma unroll
        for (int o = 16; o; o >>= 1) acc += __shfl_down_sync(0xffffffffu, acc, o);
        if (lane == 0) lgs[v] = acc;
    }
    __syncthreads();

    if (tid == 0) {
        float p[CC];
        float mx = -1e30f;
        for (int c = 0; c < CC; c++) { p[c] = lgs[c] + brc[c]; mx = fmaxf(mx, p[c]); }
        float ss = 0.f;
        for (int c = 0; c < CC; c++) { p[c] = expf(p[c] - mx); ss += p[c]; }
        for (int c = 0; c < CC; c++) p[c] /= ss;
        int i0 = 0;
        for (int c = 1; c < CC; c++) if (p[c] > p[i0]) i0 = c;
        int i1 = -1;
        for (int c = 0; c < CC; c++) if (c != i0 && (i1 < 0 || p[c] > p[i1])) i1 = c;
        float swt = p[i0] + p[i1];
        int sel[2] = { i0, i1 };
        float gv[2] = { p[i0] / swt, p[i1] / swt };

        for (int sI = 0; sI < 2; sI++) {
            int cc = sel[sI];
            g_sel[t * 2 + sI]  = cc;
            g_gate[t * 2 + sI] = gv[sI];
            float el[EE];
            for (int e = 0; e < EE; e++) el[e] = lgs[4 + cc * 4 + e] + bre[cc * EE + e];
            int e0 = 0;
            for (int e = 1; e < EE; e++) if (el[e] > el[e0]) e0 = e;
            int e1 = -1;
            for (int e = 0; e < EE; e++) if (e != e0 && (e1 < 0 || el[e] > el[e1])) e1 = e;
            float z = expf(el[e1] - el[e0]);
            float w0 = 1.f / (1.f + z), w1 = z / (1.f + z);
            int   eS[2] = { e0, e1 };
            float wS[2] = { w0, w1 };
            for (int q = 0; q < 2; q++) {
                int slot = cc * EE + eS[q];
                int pos = atomicAdd(&g_cnt[slot], 1);
                g_tok[slot * TT + pos] = t;
                g_islot[t * 4 + sI * 2 + q] = slot;
                g_ipos [t * 4 + sI * 2 + q] = pos;
                g_icoef[t * 4 + sI * 2 + q] = wS[q];
            }
        }
    }
}

// gather + input LN + tf32 round -> packed swizzled images in g_A
__global__ void prep_kernel(const float* __restrict__ x,
                            const float* __restrict__ ling, const float* __restrict__ linb)
{
    int idx = blockIdx.y;
    int i = blockIdx.x;
    if (i >= g_cnt[idx]) return;
    int tok = g_tok[idx * TT + i];
    float mu = g_mu[tok], rs = g_rstd[tok];
    const float4* xr = (const float4*)(x + (size_t)tok * DD);
    const float4* gp = (const float4*)(ling + (size_t)idx * DD);
    const float4* bp = (const float4*)(linb + (size_t)idx * DD);
    int d = threadIdx.x;   // 256: one float4 unit, dims 4d..4d+3
    float4 xv = xr[d], gv = gp[d], bv = bp[d];
    float4 o;
    o.x = tf32r((xv.x - mu) * rs * gv.x + bv.x);
    o.y = tf32r((xv.y - mu) * rs * gv.y + bv.y);
    o.z = tf32r((xv.z - mu) * rs * gv.z + bv.z);
    o.w = tf32r((xv.w - mu) * rs * gv.w + bv.w);
    // packed: [idx][ch=d>>3][mb=i>>7][4096], swizzled row (i&127), unit (d&7)
    char* dst = (char*)g_A
        + ((size_t)idx * 2097152 + (size_t)(d >> 3) * 65536 + (size_t)(i >> 7) * 4096) * 4
        + SWZ128((uint32_t)((i & 127) * 128 + (d & 7) * 16));
    *(float4*)dst = o;
}

// weight pack: in [z][R][C] (k-major rows) -> swizzled transposed images
// out layout: [idx][ch=k>>5][nb=n>>7][4096 floats]
__global__ void pack_kernel(const float* __restrict__ in, float* __restrict__ out,
                            int R, int C, int dualmap)
{
    __shared__ float t[32][33];
    int z = blockIdx.z;
    int idx = dualmap ? ((z >> 1) * 4 + ((z & 1) ? 3 : 0)) : z;
    const float* ip = in + (size_t)idx * R * C;
    float* op = out + (size_t)idx * R * C;
    int n0 = blockIdx.x * 32, k0 = blockIdx.y * 32;
    int tx = threadIdx.x & 31, ty = threadIdx.x >> 5;   // 256 thr
    #pragma unroll
    for (int i = 0; i < 4; i++)
        t[ty + 8 * i][tx] = tf32r(ip[(size_t)(k0 + ty + 8 * i) * C + n0 + tx]); // t[kloc][nloc]
    __syncthreads();
    int r_loc = threadIdx.x >> 3;   // n local 0..31
    int u = threadIdx.x & 7;        // 16B unit within row (covers k0+4u..+3)
    int n = n0 + r_loc;
    size_t base = ((size_t)(k0 >> 5) * (size_t)(C / 128) + (size_t)(n >> 7)) * 4096;
    float4 v = make_float4(t[4*u][r_loc], t[4*u+1][r_loc], t[4*u+2][r_loc], t[4*u+3][r_loc]);
    char* dst = (char*)op + base * 4 + SWZ128((uint32_t)((n & 127) * 128 + u * 16));
    *(float4*)dst = v;
}

// ================= tcgen05 machinery =================
#if TC_OK
static constexpr uint64_t SMEM_DESC_BASE_SW128 =
    (uint64_t(2)  << 61) | (uint64_t(1) << 46) | (uint64_t(64) << 32) | (uint64_t(1) << 16);
#define MAKE_SMEM_DESC(base_addr) \
    (SMEM_DESC_BASE_SW128 | ((uint64_t)((base_addr) >> 4) & 0x3FFF))
#define IDESC_TF32_N128 ((1u<<4) | (2u<<7) | (2u<<10) | ((128u/8u)<<17) | ((128u/16u)<<24))

__device__ __forceinline__ void umma_tf32(uint32_t d_tmem, uint64_t a_desc,
                                          uint64_t b_desc, uint32_t idesc, uint32_t en)
{
    asm volatile(
        "{\n\t.reg .pred p;\n\t"
        "setp.ne.u32 p, %5, 0;\n\t"
        "tcgen05.mma.cta_group::1.kind::tf32 [%0], %1, %2, %3, {%4, %4, %4, %4}, p;\n\t"
        "}"
        :: "r"(d_tmem), "l"(a_desc), "l"(b_desc), "r"(idesc), "r"(0u), "r"(en)
        : "memory");
}
__device__ __forceinline__ void bulk_g2s(uint32_t dst, const void* src,
                                         uint32_t bytes, uint32_t mbar)
{
    asm volatile(
        "cp.async.bulk.shared::cluster.global.mbarrier::complete_tx::bytes [%0], [%1], %2, [%3];\n"
        :: "r"(dst), "l"(src), "r"(bytes), "r"(mbar) : "memory");
}
#define TCGEN05_ALLOC(sa, n) \
    asm volatile("tcgen05.alloc.cta_group::1.sync.aligned.shared::cta.b32 [%0], %1;" \
        :: "r"((uint32_t)(sa)), "r"((uint32_t)(n)) : "memory")
#define TCGEN05_DEALLOC(t, n) \
    asm volatile("tcgen05.dealloc.cta_group::1.sync.aligned.b32 %0, %1;" \
        :: "r"(t), "r"((uint32_t)(n)))
#define TCGEN05_RELINQUISH() \
    asm volatile("tcgen05.relinquish_alloc_permit.cta_group::1.sync.aligned;")
#define TCGEN05_COMMIT(mb) \
    asm volatile("tcgen05.commit.cta_group::1.mbarrier::arrive::one.shared::cluster.b64 [%0];" \
        :: "r"((uint32_t)(mb)) : "memory")
#define TCGEN05_FENCE_AFTER() \
    asm volatile("tcgen05.fence::after_thread_sync;" ::: "memory")
#define TCGEN05_WAIT_LD() \
    asm volatile("tcgen05.wait::ld.sync.aligned;" ::: "memory")
#define TCGEN05_LD_X16(r, ta) \
    asm volatile( \
        "tcgen05.ld.sync.aligned.32x32b.x16.b32 " \
        "{%0, %1, %2, %3, %4, %5, %6, %7, " \
        " %8, %9, %10, %11, %12, %13, %14, %15}, [%16];" \
        : "=r"((r)[0]),  "=r"((r)[1]),  "=r"((r)[2]),  "=r"((r)[3]), \
          "=r"((r)[4]),  "=r"((r)[5]),  "=r"((r)[6]),  "=r"((r)[7]), \
          "=r"((r)[8]),  "=r"((r)[9]),  "=r"((r)[10]), "=r"((r)[11]), \
          "=r"((r)[12]), "=r"((r)[13]), "=r"((r)[14]), "=r"((r)[15]) \
        : "r"(ta))
#define MBARRIER_INIT(mb, c) \
    asm volatile("mbarrier.init.shared.b64 [%0], %1;" \
        :: "r"((uint32_t)(mb)), "r"((uint32_t)(c)) : "memory")
#define MBARRIER_EXPECT_TX(mb, bytes) \
    asm volatile("mbarrier.arrive.expect_tx.shared.b64 _, [%0], %1;" \
        :: "r"((uint32_t)(mb)), "r"((uint32_t)(bytes)) : "memory")
#define MBARRIER_INVAL(mb) \
    asm volatile("mbarrier.inval.shared.b64 [%0];" :: "r"((uint32_t)(mb)) : "memory")
#define MBAR_WAIT(mb, parity) do { \
    uint32_t _m = (uint32_t)(mb); \
    uint32_t _p = (uint32_t)(parity); \
    uint32_t _done; \
    asm volatile( \
        "{\n\t.reg .pred p;\n\t" \
        "mbarrier.try_wait.parity.acquire.cta.shared::cta.b64 p, [%1], %2;\n\t" \
        "selp.b32 %0, 1, 0, p;\n\t}" \
        : "=r"(_done) : "r"(_m), "r"(_p) : "memory"); \
    if (!_done) { \
        asm volatile( \
            "{\n\t.reg .pred P1;\n\t" \
            "WAIT_LOOP_%=:\n\t" \
            "mbarrier.try_wait.parity.acquire.cta.shared::cta.b64 P1, [%0], %1, 0x989680;\n\t" \
            "@P1 bra.uni WAIT_DONE_%=;\n\t" \
            "bra.uni WAIT_LOOP_%=;\n\t" \
            "WAIT_DONE_%=:\n\t}" \
            :: "r"(_m), "r"(_p) : "memory"); \
    } \
} while (0)
#endif

#define NSTG 3
#define ASZ 32768u
#define BSZ 32768u
#define SMEM_TC (NSTG * (ASZ + BSZ) + 1024)

// GEMM1: H = act(A @ W^T). 2 m-blocks(128) per CTA, DUAL: N=128(W1)+128(W2), else N=256 of W1.
template<bool DUAL>
__global__ void __launch_bounds__(512, 1)
gemm1_tc_kernel()
{
#if TC_OK
    int z = blockIdx.z;
    int idx = DUAL ? ((z >> 1) * 4 + ((z & 1) ? 3 : 0))
                   : ((z >> 1) * 4 + ((z & 1) ? 2 : 1));
    int Nt = g_cnt[idx];
    int m0 = blockIdx.y * 256;
    if (m0 >= Nt) return;
    const int NCOLS = DUAL ? 128 : 256;
    int n0 = blockIdx.x * NCOLS;

    const float* Aimg  = g_A   + (size_t)idx * 2097152;
    const float* B1img = g_W1t + (size_t)idx * 2097152;
    const float* B2img = g_W2t + (size_t)idx * 2097152;

    extern __shared__ __align__(1024) char smem[];
    uint32_t sb = smem_u32(smem);
    uint32_t aBase = sb;
    uint32_t bBase = sb + NSTG * ASZ;
    uint32_t ctrl  = bBase + NSTG * BSZ;   // [0]=tmem, [8]=mma mbar, [16+8s]=full[s]

    int tid = threadIdx.x;
    int w = tid >> 5;

    if (w == 0) TCGEN05_ALLOC(ctrl, 512);
    if (tid == 0) {
        MBARRIER_INIT(ctrl + 8, 1);
        #pragma unroll
        for (int s2 = 0; s2 < NSTG; ++s2) MBARRIER_INIT(ctrl + 16 + 8 * s2, 1);
    }
    __syncthreads();
    uint32_t tmem;
    asm volatile("ld.shared.b32 %0, [%1];" : "=r"(tmem) : "r"(ctrl));

    const int NCH = DD / 32;   // 32
    if (tid == 0) {
        auto load_chunk = [&](int st, int ch) {
            uint32_t mb = ctrl + 16 + 8 * st;
            MBARRIER_EXPECT_TX(mb, (uint32_t)(ASZ + BSZ));
            // A: mb-pair contiguous 32KB
            bulk_g2s(aBase + st * ASZ,
                     Aimg + (size_t)ch * 65536 + (size_t)(m0 >> 7) * 4096, ASZ, mb);
            if (DUAL) {
                bulk_g2s(bBase + st * BSZ,
                         B1img + (size_t)ch * 65536 + (size_t)(n0 >> 7) * 4096, 16384, mb);
                bulk_g2s(bBase + st * BSZ + 16384,
                         B2img + (size_t)ch * 65536 + (size_t)(n0 >> 7) * 4096, 16384, mb);
            } else {
                bulk_g2s(bBase + st * BSZ,
                         B1img + (size_t)ch * 65536 + (size_t)(n0 >> 7) * 4096, BSZ, mb);
            }
        };
        load_chunk(0, 0);
        load_chunk(1, 1);
        for (int it = 0; it < NCH; ++it) {
            int st = it % NSTG;
            MBAR_WAIT(ctrl + 16 + 8 * st, (it / NSTG) & 1);
            #pragma unroll
            for (int m = 0; m < 2; ++m) {
                uint64_t ad = MAKE_SMEM_DESC(aBase + st * ASZ + m * 16384u);
                #pragma unroll
                for (int half = 0; half < 2; ++half) {
                    uint64_t bd = MAKE_SMEM_DESC(bBase + st * BSZ + half * 16384u);
                    #pragma unroll
                    for (int k = 0; k < 4; ++k)
                        umma_tf32(tmem + m * 256 + half * 128, ad + 2 * k, bd + 2 * k,
                                  IDESC_TF32_N128, (uint32_t)(it > 0 || k > 0));
                }
            }
            TCGEN05_COMMIT(ctrl + 8);
            if (it >= 1) MBAR_WAIT(ctrl + 8, (it - 1) & 1);
            if (it + 2 < NCH) load_chunk((it + 2) % NSTG, it + 2);
        }
        MBAR_WAIT(ctrl + 8, (NCH - 1) & 1);
    }
    __syncthreads();
    TCGEN05_FENCE_AFTER();

    // epilogue -> packed g_H images
    int lane = tid & 31;
    int sub = w & 3, grp = w >> 2;
    int act = (idx & 3) % 3;
    float* Hb = g_H + (size_t)idx * 4194304;
    #pragma unroll
    for (int mblk = 0; mblk < 2; ++mblk) {
        int mrow = m0 + mblk * 128 + sub * 32 + lane;
        bool valid = mrow < Nt;
        uint32_t tb = tmem + mblk * 256;
        const int NCC = DUAL ? 2 : 4;
        #pragma unroll
        for (int cc = 0; cc < 4; ++cc) {
            if (cc >= NCC) break;
            int fbase = n0 + (DUAL ? grp * 32 + cc * 16 : grp * 64 + cc * 16);
            uint32_t d1[16], d2[16];
            TCGEN05_LD_X16(d1, tb + (DUAL ? grp * 32 + cc * 16 : grp * 64 + cc * 16));
            if (DUAL) { TCGEN05_LD_X16(d2, tb + 128 + grp * 32 + cc * 16); }
            TCGEN05_WAIT_LD();
            if (valid) {
                #pragma unroll
                for (int v = 0; v < 4; ++v) {
                    float hv[4];
                    #pragma unroll
                    for (int j = 0; j < 4; ++j) {
                        float h1 = __uint_as_float(d1[4 * v + j]);
                        float r;
                        if (DUAL) {
                            float h2 = __uint_as_float(d2[4 * v + j]);
                            float sg = 1.f / (1.f + expf(-h2));
                            r = h2 * sg * h2 * h1;
                        } else if (act == 1) {
                            r = 0.5f * h1 * (1.f + erff(h1 * 0.70710678118654752f));
                        } else {
                            r = fmaxf(h1, 0.f);
                        }
                        hv[j] = tf32r(r);
                    }
                    int f = fbase + 4 * v;
                    char* dst = (char*)Hb
                        + ((size_t)(f >> 5) * 65536 + (size_t)(mrow >> 7) * 4096) * 4
                        + SWZ128((uint32_t)((mrow & 127) * 128 + ((f & 31) >> 2) * 16));
                    *(float4*)dst = make_float4(hv[0], hv[1], hv[2], hv[3]);
                }
            }
        }
    }
    __syncthreads();
    if (tid == 0) {
        MBARRIER_INVAL(ctrl + 8);
        #pragma unroll
        for (int s2 = 0; s2 < NSTG; ++s2) MBARRIER_INVAL(ctrl + 16 + 8 * s2);
    }
    if (w == 0) { TCGEN05_RELINQUISH(); TCGEN05_DEALLOC(tmem, 512); }
#endif
}

// GEMM2: Z = x + H @ W3^T. 2 m-blocks x 256 n-cols, K=FF.
__global__ void __launch_bounds__(512, 1)
gemm2_tc_kernel(const float* __restrict__ x)
{
#if TC_OK
    int idx = blockIdx.z;
    int Nt = g_cnt[idx];
    int m0 = blockIdx.y * 256;
    if (m0 >= Nt) return;
    int n0 = blockIdx.x * 256;

    const float* Aimg = g_H   + (size_t)idx * 4194304;
    const float* Bimg = g_W3t + (size_t)idx * 2097152;

    extern __shared__ __align__(1024) char smem[];
    uint32_t sb = smem_u32(smem);
    uint32_t aBase = sb;
    uint32_t bBase = sb + NSTG * ASZ;
    uint32_t ctrl  = bBase + NSTG * BSZ;

    int tid = threadIdx.x;
    int w = tid >> 5;

    if (w == 0) TCGEN05_ALLOC(ctrl, 512);
    if (tid == 0) {
        MBARRIER_INIT(ctrl + 8, 1);
        #pragma unroll
        for (int s2 = 0; s2 < NSTG; ++s2) MBARRIER_INIT(ctrl + 16 + 8 * s2, 1);
    }
    __syncthreads();
    uint32_t tmem;
    asm volatile("ld.shared.b32 %0, [%1];" : "=r"(tmem) : "r"(ctrl));

    const int NCH = FF / 32;   // 64
    if (tid == 0) {
        auto load_chunk = [&](int st, int ch) {
            uint32_t mb = ctrl + 16 + 8 * st;
            MBARRIER_EXPECT_TX(mb, (uint32_t)(ASZ + BSZ));
            bulk_g2s(aBase + st * ASZ,
                     Aimg + (size_t)ch * 65536 + (size_t)(m0 >> 7) * 4096, ASZ, mb);
            bulk_g2s(bBase + st * BSZ,
                     Bimg + (size_t)ch * 32768 + (size_t)(n0 >> 7) * 4096, BSZ, mb);
        };
        load_chunk(0, 0);
        load_chunk(1, 1);
        for (int it = 0; it < NCH; ++it) {
            int st = it % NSTG;
            MBAR_WAIT(ctrl + 16 + 8 * st, (it / NSTG) & 1);
            #pragma unroll
            for (int m = 0; m < 2; ++m) {
                uint64_t ad = MAKE_SMEM_DESC(aBase + st * ASZ + m * 16384u);
                #pragma unroll
                for (int half = 0; half < 2; ++half) {
                    uint64_t bd = MAKE_SMEM_DESC(bBase + st * BSZ + half * 16384u);
                    #pragma unroll
                    for (int k = 0; k < 4; ++k)
                        umma_tf32(tmem + m * 256 + half * 128, ad + 2 * k, bd + 2 * k,
                                  IDESC_TF32_N128, (uint32_t)(it > 0 || k > 0));
                }
            }
            TCGEN05_COMMIT(ctrl + 8);
            if (it >= 1) MBAR_WAIT(ctrl + 8, (it - 1) & 1);
            if (it + 2 < NCH) load_chunk((it + 2) % NSTG, it + 2);
        }
        MBAR_WAIT(ctrl + 8, (NCH - 1) & 1);
    }
    __syncthreads();
    TCGEN05_FENCE_AFTER();

    int lane = tid & 31;
    int sub = w & 3, grp = w >> 2;
    float* Zb = g_Z + (size_t)idx * TT * DD;
    #pragma unroll
    for (int mblk = 0; mblk < 2; ++mblk) {
        int mrow = m0 + mblk * 128 + sub * 32 + lane;
        bool valid = mrow < Nt;
        int tok = valid ? g_tok[idx * TT + mrow] : 0;
        uint32_t tb = tmem + mblk * 256;
        #pragma unroll
        for (int cc = 0; cc < 4; ++cc) {
            uint32_t d1[16];
            TCGEN05_LD_X16(d1, tb + grp * 64 + cc * 16);
            TCGEN05_WAIT_LD();
            if (valid) {
                const float4* xr = (const float4*)(x + (size_t)tok * DD + n0 + grp * 64 + cc * 16);
                float4* p = (float4*)(Zb + (size_t)mrow * DD + n0 + grp * 64 + cc * 16);
                #pragma unroll
                for (int v = 0; v < 4; ++v) {
                    float4 xv = xr[v];
                    p[v] = make_float4(__uint_as_float(d1[4*v])   + xv.x,
                                       __uint_as_float(d1[4*v+1]) + xv.y,
                                       __uint_as_float(d1[4*v+2]) + xv.z,
                                       __uint_as_float(d1[4*v+3]) + xv.w);
                }
            }
        }
    }
    __syncthreads();
    if (tid == 0) {
        MBARRIER_INVAL(ctrl + 8);
        #pragma unroll
        for (int s2 = 0; s2 < NSTG; ++s2) MBARRIER_INVAL(ctrl + 16 + 8 * s2);
    }
    if (w == 0) { TCGEN05_RELINQUISH(); TCGEN05_DEALLOC(tmem, 512); }
#endif
}

// fused: expert LN + expert combine + cluster LN + gate sum
__global__ void final_kernel(const float* __restrict__ loutg, const float* __restrict__ loutb,
                             const float* __restrict__ clng, const float* __restrict__ clnb,
                             float* __restrict__ out)
{
    int t = blockIdx.x;
    int tid = threadIdx.x;                    // 256
    __shared__ float rbuf[18];
    float o[4] = {};
    #pragma unroll
    for (int sI = 0; sI < 2; sI++) {
        float vcmb[4] = {};
        #pragma unroll
        for (int q = 0; q < 2; q++) {
            int slot = g_islot[t * 4 + sI * 2 + q];
            int pos  = g_ipos [t * 4 + sI * 2 + q];
            float cf = g_icoef[t * 4 + sI * 2 + q];
            const float* y = g_Z + ((size_t)slot * TT + pos) * DD;
            const float* gp = loutg + (size_t)slot * DD;
            const float* bp = loutb + (size_t)slot * DD;
            float v[4], s = 0.f, s2 = 0.f;
            #pragma unroll
            for (int r = 0; r < 4; r++) {
                int d = tid + 256 * r;
                v[r] = y[d]; s += v[r]; s2 += v[r] * v[r];
            }
            float mu, rs;
            block_meanvar_256(s, s2, rbuf, mu, rs);
            #pragma unroll
            for (int r = 0; r < 4; r++) {
                int d = tid + 256 * r;
                vcmb[r] += cf * ((v[r] - mu) * rs * gp[d] + bp[d]);
            }
        }
        float s = 0.f, s2 = 0.f;
        #pragma unroll
        for (int r = 0; r < 4; r++) { s += vcmb[r]; s2 += vcmb[r] * vcmb[r]; }
        float mu, rs;
        block_meanvar_256(s, s2, rbuf, mu, rs);
        int cc = g_sel[t * 2 + sI];
        float gt = g_gate[t * 2 + sI];
        #pragma unroll
        for (int r = 0; r < 4; r++) {
            int d = tid + 256 * r;
            o[r] += gt * ((vcmb[r] - mu) * rs * clng[cc * DD + d] + clnb[cc * DD + d]);
        }
    }
    #pragma unroll
    for (int r = 0; r < 4; r++)
        out[(size_t)t * DD + tid + 256 * r] = o[r];
}

// ---------------- launcher ----------------
extern "C" void kernel_launch(void* const* d_in, const int* in_sizes, int n_in,
                              void* d_out, int out_size)
{
    const float* x     = (const float*)d_in[0];
    const float* W1    = (const float*)d_in[1];
    const float* W2    = (const float*)d_in[2];
    const float* W3    = (const float*)d_in[3];
    const float* ling  = (const float*)d_in[4];
    const float* linb  = (const float*)d_in[5];
    const float* loutg = (const float*)d_in[6];
    const float* loutb = (const float*)d_in[7];
    const float* clng  = (const float*)d_in[8];
    const float* clnb  = (const float*)d_in[9];
    const float* Wrc   = (const float*)d_in[10];
    const float* brc   = (const float*)d_in[11];
    const float* Wre   = (const float*)d_in[12];
    const float* bre   = (const float*)d_in[13];
    float* out = (float*)d_out;

    float* w1t; cudaGetSymbolAddress((void**)&w1t, g_W1t);
    float* w2t; cudaGetSymbolAddress((void**)&w2t, g_W2t);
    float* w3t; cudaGetSymbolAddress((void**)&w3t, g_W3t);

    cudaFuncSetAttribute(gemm1_tc_kernel<true>,
                         cudaFuncAttributeMaxDynamicSharedMemorySize, SMEM_TC);
    cudaFuncSetAttribute(gemm1_tc_kernel<false>,
                         cudaFuncAttributeMaxDynamicSharedMemorySize, SMEM_TC);
    cudaFuncSetAttribute(gemm2_tc_kernel,
                         cudaFuncAttributeMaxDynamicSharedMemorySize, SMEM_TC);

    // launch order chosen so ncu (-s 5 -c 1) profiles gemm1_tc<true> (launch #6)
    zero_cnt_kernel<<<1, 32>>>();                                        // 1
    routing_kernel<<<TT, 128>>>(x, Wrc, brc, Wre, bre);                  // 2
    dim3 gp(TT, NEXP);
    prep_kernel<<<gp, 256>>>(x, ling, linb);                             // 3
    pack_kernel<<<dim3(FF/32, DD/32, 16), 256>>>(W1, w1t, DD, FF, 0);    // 4
    pack_kernel<<<dim3(FF/32, DD/32, 8),  256>>>(W2, w2t, DD, FF, 1);    // 5

    dim3 g1d(FF/128, TT/256, 8);
    gemm1_tc_kernel<true><<<g1d, 512, SMEM_TC>>>();                      // 6 <- profiled
    dim3 g1s(FF/256, TT/256, 8);
    gemm1_tc_kernel<false><<<g1s, 512, SMEM_TC>>>();                     // 7

    pack_kernel<<<dim3(DD/32, FF/32, 16), 256>>>(W3, w3t, FF, DD, 0);    // 8
    dim3 g2(DD/256, TT/256, NEXP);
    gemm2_tc_kernel<<<g2, 512, SMEM_TC>>>(x);                            // 9

    final_kernel<<<TT, 256>>>(loutg, loutb, clng, clnb, out);            // 10
}

// round 10
// speedup vs baseline: 1.5680x; 1.0445x over previous
#include <cuda_runtime.h>
#include <math.h>
#include <stdint.h>

#define TT 2048
#define DD 1024
#define FF 2048
#define CC 4
#define EE 4
#define NEXP 16
#define EPSL 1e-5f

#if defined(__CUDA_ARCH_FEAT_SM103_ALL) || defined(__CUDA_ARCH_FEAT_SM100_ALL) || \
    (defined(__CUDA_ARCH_SPECIFIC__) && (__CUDA_ARCH_SPECIFIC__ >= 1000))
#define TC_OK 1
#else
#define TC_OK 0
#endif

// ---------------- device scratch (packed swizzled tile images) ----------------
// g_A  : [idx][ch(32)][mb(16)][4096 floats]
// g_H  : [idx][ch(64)][mb(16)][4096 floats]
// g_W1t: [idx][ch(32)][nb(16)][4096 floats]
// g_W2t: [idx][ch(32)][nb(16)][4096 floats]
// g_W3t: [idx][ch(64)][nb(8) ][4096 floats]
__device__ float g_A[16ULL*2048ULL*1024ULL];
__device__ float g_H[16ULL*2048ULL*2048ULL];
__device__ float g_Z[16ULL*2048ULL*1024ULL];
__device__ float g_W1t[16ULL*2048ULL*1024ULL];
__device__ float g_W2t[16ULL*2048ULL*1024ULL];
__device__ float g_W3t[16ULL*1024ULL*2048ULL];
__device__ int   g_cnt[NEXP];
__device__ int   g_tok[NEXP*TT];
__device__ int   g_sel[TT*2];
__device__ float g_gate[TT*2];
__device__ int   g_islot[TT*4];
__device__ int   g_ipos[TT*4];
__device__ float g_icoef[TT*4];

// ---------------- helpers ----------------
__device__ __forceinline__ float tf32r(float f) {
    uint32_t r;
    asm("cvt.rna.tf32.f32 %0, %1;" : "=r"(r) : "f"(f));
    return __uint_as_float(r);
}
__device__ __forceinline__ uint32_t smem_u32(const void* p) {
    uint32_t a;
    asm("{ .reg .u64 t; cvta.to.shared.u64 t, %1; cvt.u32.u64 %0, t; }" : "=r"(a) : "l"(p));
    return a;
}
#define SWZ128(off) ((off) ^ (((off) >> 3) & 0x70))

__device__ __forceinline__ void block_meanvar_256(float s, float s2, float* rbuf,
                                                  float& mu, float& rs)
{
    int tid = threadIdx.x, lane = tid & 31, w = tid >> 5;
    __syncthreads();
    #pragma unroll
    for (int o = 16; o; o >>= 1) {
        s  += __shfl_down_sync(0xffffffffu, s,  o);
        s2 += __shfl_down_sync(0xffffffffu, s2, o);
    }
    if (lane == 0) { rbuf[w] = s; rbuf[8 + w] = s2; }
    __syncthreads();
    if (tid == 0) {
        float S = 0.f, S2 = 0.f;
        #pragma unroll
        for (int ww = 0; ww < 8; ww++) { S += rbuf[ww]; S2 += rbuf[8 + ww]; }
        float m = S / (float)DD;
        rbuf[16] = m;
        rbuf[17] = rsqrtf(S2 / (float)DD - m * m + EPSL);
    }
    __syncthreads();
    mu = rbuf[16];
    rs = rbuf[17];
}

// ---------------- small kernels ----------------
__global__ void zero_cnt_kernel()
{
    if (threadIdx.x < NEXP) g_cnt[threadIdx.x] = 0;
}

// routing + fused prep: computes top-2/top-2 routing and scatters the LN'd,
// tf32-rounded token row directly into the 4 packed g_A expert images.
__global__ void routing_kernel(const float* __restrict__ x,
                               const float* __restrict__ Wrc, const float* __restrict__ brc,
                               const float* __restrict__ Wre, const float* __restrict__ bre,
                               const float* __restrict__ ling, const float* __restrict__ linb)
{
    int t = blockIdx.x;
    __shared__ float xs[DD];
    __shared__ float rbuf[18];
    __shared__ float lgs[20];
    __shared__ int   sslot[4];
    __shared__ int   spos[4];
    int tid = threadIdx.x;          // 128
    int lane = tid & 31, wid = tid >> 5;

    float s = 0.f, s2 = 0.f;
    for (int d = tid; d < DD; d += 128) {
        float v = x[(size_t)t * DD + d];
        xs[d] = v; s += v; s2 += v * v;
    }
    #pragma unroll
    for (int o = 16; o; o >>= 1) {
        s  += __shfl_down_sync(0xffffffffu, s,  o);
        s2 += __shfl_down_sync(0xffffffffu, s2, o);
    }
    if (lane == 0) { rbuf[wid] = s; rbuf[8 + wid] = s2; }
    __syncthreads();
    if (tid == 0) {
        float S  = rbuf[0] + rbuf[1] + rbuf[2] + rbuf[3];
        float S2 = rbuf[8] + rbuf[9] + rbuf[10] + rbuf[11];
        float mu = S / (float)DD;
        rbuf[16] = mu;
        rbuf[17] = rsqrtf(S2 / (float)DD - mu * mu + EPSL);
    }

    for (int v = wid; v < 20; v += 4) {
        float acc = 0.f;
        if (v < CC) {
            for (int d = lane; d < DD; d += 32) acc += xs[d] * Wrc[d * CC + v];
        } else {
            int cc = (v - 4) >> 2, e = (v - 4) & 3;
            const float* wp = Wre + (size_t)cc * DD * EE + e;
            for (int d = lane; d < DD; d += 32) acc += xs[d] * wp[d * EE];
        }
        #pragma unroll
        for (int o = 16; o; o >>= 1) acc += __shfl_down_sync(0xffffffffu, acc, o);
        if (lane == 0) lgs[v] = acc;
    }
    __syncthreads();

    if (tid == 0) {
        float p[CC];
        float mx = -1e30f;
        for (int c = 0; c < CC; c++) { p[c] = lgs[c] + brc[c]; mx = fmaxf(mx, p[c]); }
        float ss = 0.f;
        for (int c = 0; c < CC; c++) { p[c] = expf(p[c] - mx); ss += p[c]; }
        for (int c = 0; c < CC; c++) p[c] /= ss;
        int i0 = 0;
        for (int c = 1; c < CC; c++) if (p[c] > p[i0]) i0 = c;
        int i1 = -1;
        for (int c = 0; c < CC; c++) if (c != i0 && (i1 < 0 || p[c] > p[i1])) i1 = c;
        float swt = p[i0] + p[i1];
        int sel[2] = { i0, i1 };
        float gv[2] = { p[i0] / swt, p[i1] / swt };

        for (int sI = 0; sI < 2; sI++) {
            int cc = sel[sI];
            g_sel[t * 2 + sI]  = cc;
            g_gate[t * 2 + sI] = gv[sI];
            float el[EE];
            for (int e = 0; e < EE; e++) el[e] = lgs[4 + cc * 4 + e] + bre[cc * EE + e];
            int e0 = 0;
            for (int e = 1; e < EE; e++) if (el[e] > el[e0]) e0 = e;
            int e1 = -1;
            for (int e = 0; e < EE; e++) if (e != e0 && (e1 < 0 || el[e] > el[e1])) e1 = e;
            float z = expf(el[e1] - el[e0]);
            float w0 = 1.f / (1.f + z), w1 = z / (1.f + z);
            int   eS[2] = { e0, e1 };
            float wS[2] = { w0, w1 };
            for (int q = 0; q < 2; q++) {
                int slot = cc * EE + eS[q];
                int pos = atomicAdd(&g_cnt[slot], 1);
                g_tok[slot * TT + pos] = t;
                g_islot[t * 4 + sI * 2 + q] = slot;
                g_ipos [t * 4 + sI * 2 + q] = pos;
                g_icoef[t * 4 + sI * 2 + q] = wS[q];
                sslot[sI * 2 + q] = slot;
                spos [sI * 2 + q] = pos;
            }
        }
    }
    __syncthreads();

    // fused prep: scatter LN'd row into 4 packed g_A images
    float mu = rbuf[16], rs = rbuf[17];
    #pragma unroll
    for (int q = 0; q < 4; q++) {
        int slot = sslot[q];
        int pos  = spos[q];
        const float4* gp = (const float4*)(ling + (size_t)slot * DD);
        const float4* bp = (const float4*)(linb + (size_t)slot * DD);
        #pragma unroll
        for (int r = 0; r < 2; r++) {
            int u = tid + 128 * r;    // float4 unit 0..255
            float4 xv = *(const float4*)&xs[4 * u];
            float4 gv = gp[u], bv = bp[u];
            float4 o;
            o.x = tf32r((xv.x - mu) * rs * gv.x + bv.x);
            o.y = tf32r((xv.y - mu) * rs * gv.y + bv.y);
            o.z = tf32r((xv.z - mu) * rs * gv.z + bv.z);
            o.w = tf32r((xv.w - mu) * rs * gv.w + bv.w);
            char* dst = (char*)g_A
                + ((size_t)slot * 2097152 + (size_t)(u >> 3) * 65536
                   + (size_t)(pos >> 7) * 4096) * 4
                + SWZ128((uint32_t)((pos & 127) * 128 + (u & 7) * 16));
            *(float4*)dst = o;
        }
    }
}

// weight pack: in [z][R][C] (k-major rows) -> swizzled transposed images
__global__ void pack_kernel(const float* __restrict__ in, float* __restrict__ out,
                            int R, int C, int dualmap)
{
    __shared__ float t[32][33];
    int z = blockIdx.z;
    int idx = dualmap ? ((z >> 1) * 4 + ((z & 1) ? 3 : 0)) : z;
    const float* ip = in + (size_t)idx * R * C;
    float* op = out + (size_t)idx * R * C;
    int n0 = blockIdx.x * 32, k0 = blockIdx.y * 32;
    int tx = threadIdx.x & 31, ty = threadIdx.x >> 5;   // 256 thr
    #pragma unroll
    for (int i = 0; i < 4; i++)
        t[ty + 8 * i][tx] = tf32r(ip[(size_t)(k0 + ty + 8 * i) * C + n0 + tx]);
    __syncthreads();
    int r_loc = threadIdx.x >> 3;
    int u = threadIdx.x & 7;
    int n = n0 + r_loc;
    size_t base = ((size_t)(k0 >> 5) * (size_t)(C / 128) + (size_t)(n >> 7)) * 4096;
    float4 v = make_float4(t[4*u][r_loc], t[4*u+1][r_loc], t[4*u+2][r_loc], t[4*u+3][r_loc]);
    char* dst = (char*)op + base * 4 + SWZ128((uint32_t)((n & 127) * 128 + u * 16));
    *(float4*)dst = v;
}

// ================= tcgen05 machinery =================
#if TC_OK
static constexpr uint64_t SMEM_DESC_BASE_SW128 =
    (uint64_t(2)  << 61) | (uint64_t(1) << 46) | (uint64_t(64) << 32) | (uint64_t(1) << 16);
#define MAKE_SMEM_DESC(base_addr) \
    (SMEM_DESC_BASE_SW128 | ((uint64_t)((base_addr) >> 4) & 0x3FFF))
#define IDESC_TF32_N128 ((1u<<4) | (2u<<7) | (2u<<10) | ((128u/8u)<<17) | ((128u/16u)<<24))

__device__ __forceinline__ void umma_tf32(uint32_t d_tmem, uint64_t a_desc,
                                          uint64_t b_desc, uint32_t idesc, uint32_t en)
{
    asm volatile(
        "{\n\t.reg .pred p;\n\t"
        "setp.ne.u32 p, %5, 0;\n\t"
        "tcgen05.mma.cta_group::1.kind::tf32 [%0], %1, %2, %3, {%4, %4, %4, %4}, p;\n\t"
        "}"
        :: "r"(d_tmem), "l"(a_desc), "l"(b_desc), "r"(idesc), "r"(0u), "r"(en)
        : "memory");
}
__device__ __forceinline__ void bulk_g2s(uint32_t dst, const void* src,
                                         uint32_t bytes, uint32_t mbar)
{
    asm volatile(
        "cp.async.bulk.shared::cluster.global.mbarrier::complete_tx::bytes [%0], [%1], %2, [%3];\n"
        :: "r"(dst), "l"(src), "r"(bytes), "r"(mbar) : "memory");
}
#define TCGEN05_ALLOC(sa, n) \
    asm volatile("tcgen05.alloc.cta_group::1.sync.aligned.shared::cta.b32 [%0], %1;" \
        :: "r"((uint32_t)(sa)), "r"((uint32_t)(n)) : "memory")
#define TCGEN05_DEALLOC(t, n) \
    asm volatile("tcgen05.dealloc.cta_group::1.sync.aligned.b32 %0, %1;" \
        :: "r"(t), "r"((uint32_t)(n)))
#define TCGEN05_RELINQUISH() \
    asm volatile("tcgen05.relinquish_alloc_permit.cta_group::1.sync.aligned;")
#define TCGEN05_COMMIT(mb) \
    asm volatile("tcgen05.commit.cta_group::1.mbarrier::arrive::one.shared::cluster.b64 [%0];" \
        :: "r"((uint32_t)(mb)) : "memory")
#define TCGEN05_FENCE_AFTER() \
    asm volatile("tcgen05.fence::after_thread_sync;" ::: "memory")
#define TCGEN05_WAIT_LD() \
    asm volatile("tcgen05.wait::ld.sync.aligned;" ::: "memory")
#define TCGEN05_LD_X16(r, ta) \
    asm volatile( \
        "tcgen05.ld.sync.aligned.32x32b.x16.b32 " \
        "{%0, %1, %2, %3, %4, %5, %6, %7, " \
        " %8, %9, %10, %11, %12, %13, %14, %15}, [%16];" \
        : "=r"((r)[0]),  "=r"((r)[1]),  "=r"((r)[2]),  "=r"((r)[3]), \
          "=r"((r)[4]),  "=r"((r)[5]),  "=r"((r)[6]),  "=r"((r)[7]), \
          "=r"((r)[8]),  "=r"((r)[9]),  "=r"((r)[10]), "=r"((r)[11]), \
          "=r"((r)[12]), "=r"((r)[13]), "=r"((r)[14]), "=r"((r)[15]) \
        : "r"(ta))
#define MBARRIER_INIT(mb, c) \
    asm volatile("mbarrier.init.shared.b64 [%0], %1;" \
        :: "r"((uint32_t)(mb)), "r"((uint32_t)(c)) : "memory")
#define MBARRIER_EXPECT_TX(mb, bytes) \
    asm volatile("mbarrier.arrive.expect_tx.shared.b64 _, [%0], %1;" \
        :: "r"((uint32_t)(mb)), "r"((uint32_t)(bytes)) : "memory")
#define MBARRIER_INVAL(mb) \
    asm volatile("mbarrier.inval.shared.b64 [%0];" :: "r"((uint32_t)(mb)) : "memory")
#define MBAR_WAIT(mb, parity) do { \
    uint32_t _m = (uint32_t)(mb); \
    uint32_t _p = (uint32_t)(parity); \
    uint32_t _done; \
    asm volatile( \
        "{\n\t.reg .pred p;\n\t" \
        "mbarrier.try_wait.parity.acquire.cta.shared::cta.b64 p, [%1], %2;\n\t" \
        "selp.b32 %0, 1, 0, p;\n\t}" \
        : "=r"(_done) : "r"(_m), "r"(_p) : "memory"); \
    if (!_done) { \
        asm volatile( \
            "{\n\t.reg .pred P1;\n\t" \
            "WAIT_LOOP_%=:\n\t" \
            "mbarrier.try_wait.parity.acquire.cta.shared::cta.b64 P1, [%0], %1, 0x989680;\n\t" \
            "@P1 bra.uni WAIT_DONE_%=;\n\t" \
            "bra.uni WAIT_LOOP_%=;\n\t" \
            "WAIT_DONE_%=:\n\t}" \
            :: "r"(_m), "r"(_p) : "memory"); \
    } \
} while (0)
#endif

#define NSTG 3
#define STGB 65536u            // stage stride: A 32KB + B 32KB
#define SMEM_TC (NSTG * STGB + 1024)

// GEMM1 (merged dual+single): H = act(A @ W^T).
// grid (16, 8, 16): n0 = x*128 f-cols, m0 = y*256 rows, z = expert idx.
__global__ void __launch_bounds__(512, 1)
gemm1_tc_kernel()
{
#if TC_OK
    int idx = blockIdx.z;
    bool dual = ((idx & 3) % 3) == 0;
    int act = (idx & 3) % 3;
    int Nt = g_cnt[idx];
    int m0 = blockIdx.y * 256;
    if (m0 >= Nt) return;
    int n0 = blockIdx.x * 128;

    const float* Aimg  = g_A   + (size_t)idx * 2097152;
    const float* B1img = g_W1t + (size_t)idx * 2097152;
    const float* B2img = g_W2t + (size_t)idx * 2097152;

    extern __shared__ __align__(1024) char smem[];
    uint32_t sb = smem_u32(smem);
    uint32_t ctrl = sb + NSTG * STGB;   // [0]=tmem, [8]=mma mbar, [16+8s]=full[s]

    int tid = threadIdx.x;
    int w = tid >> 5;

    if (w == 0) TCGEN05_ALLOC(ctrl, 512);
    if (tid == 0) {
        MBARRIER_INIT(ctrl + 8, 1);
        #pragma unroll
        for (int s2 = 0; s2 < NSTG; ++s2) MBARRIER_INIT(ctrl + 16 + 8 * s2, 1);
    }
    __syncthreads();
    uint32_t tmem;
    asm volatile("ld.shared.b32 %0, [%1];" : "=r"(tmem) : "r"(ctrl));

    const int NCH = DD / 32;   // 32
    if (tid == 0) {
        uint32_t txbytes = 32768u + 16384u + (dual ? 16384u : 0u);
        auto load_chunk = [&](int st, int ch) {
            uint32_t mb = ctrl + 16 + 8 * st;
            uint32_t base = sb + st * STGB;
            MBARRIER_EXPECT_TX(mb, txbytes);
            bulk_g2s(base, Aimg + (size_t)ch * 65536 + (size_t)(m0 >> 7) * 4096, 32768, mb);
            bulk_g2s(base + 32768, B1img + (size_t)ch * 65536 + (size_t)(n0 >> 7) * 4096, 16384, mb);
            if (dual)
                bulk_g2s(base + 49152, B2img + (size_t)ch * 65536 + (size_t)(n0 >> 7) * 4096, 16384, mb);
        };
        load_chunk(0, 0);
        load_chunk(1, 1);
        for (int it = 0; it < NCH; ++it) {
            int st = it % NSTG;
            // free buffer (it+2)%3 (used by mma batch it-1) and prefetch EARLY
            if (it >= 1) MBAR_WAIT(ctrl + 8, (it - 1) & 1);
            if (it + 2 < NCH) load_chunk((it + 2) % NSTG, it + 2);
            MBAR_WAIT(ctrl + 16 + 8 * st, (it / NSTG) & 1);
            uint32_t base = sb + st * STGB;
            #pragma unroll
            for (int m = 0; m < 2; ++m) {
                uint64_t ad = MAKE_SMEM_DESC(base + m * 16384u);
                uint64_t bd = MAKE_SMEM_DESC(base + 32768u);
                #pragma unroll
                for (int k = 0; k < 4; ++k)
                    umma_tf32(tmem + m * 256, ad + 2 * k, bd + 2 * k,
                              IDESC_TF32_N128, (uint32_t)(it > 0 || k > 0));
                if (dual) {
                    uint64_t bd2 = MAKE_SMEM_DESC(base + 49152u);
                    #pragma unroll
                    for (int k = 0; k < 4; ++k)
                        umma_tf32(tmem + m * 256 + 128, ad + 2 * k, bd2 + 2 * k,
                                  IDESC_TF32_N128, (uint32_t)(it > 0 || k > 0));
                }
            }
            TCGEN05_COMMIT(ctrl + 8);
        }
        MBAR_WAIT(ctrl + 8, (NCH - 1) & 1);
    }
    __syncthreads();
    TCGEN05_FENCE_AFTER();

    // epilogue -> packed g_H images.  warp grp covers 32 f-cols of the 128-tile.
    int lane = tid & 31;
    int sub = w & 3, grp = w >> 2;
    float* Hb = g_H + (size_t)idx * 4194304;
    #pragma unroll
    for (int mblk = 0; mblk < 2; ++mblk) {
        int mrow = m0 + mblk * 128 + sub * 32 + lane;
        bool valid = mrow < Nt;
        uint32_t tb = tmem + mblk * 256;
        #pragma unroll
        for (int cc = 0; cc < 2; ++cc) {
            int fbase = n0 + grp * 32 + cc * 16;
            uint32_t d1[16], d2[16];
            TCGEN05_LD_X16(d1, tb + grp * 32 + cc * 16);
            if (dual) { TCGEN05_LD_X16(d2, tb + 128 + grp * 32 + cc * 16); }
            TCGEN05_WAIT_LD();
            if (valid) {
                #pragma unroll
                for (int v = 0; v < 4; ++v) {
                    float hv[4];
                    #pragma unroll
                    for (int j = 0; j < 4; ++j) {
                        float h1 = __uint_as_float(d1[4 * v + j]);
                        float r;
                        if (dual) {
                            float h2 = __uint_as_float(d2[4 * v + j]);
                            float sg = 1.f / (1.f + expf(-h2));
                            r = h2 * sg * h2 * h1;
                        } else if (act == 1) {
                            r = 0.5f * h1 * (1.f + erff(h1 * 0.70710678118654752f));
                        } else {
                            r = fmaxf(h1, 0.f);
                        }
                        hv[j] = tf32r(r);
                    }
                    int f = fbase + 4 * v;
                    char* dst = (char*)Hb
                        + ((size_t)(f >> 5) * 65536 + (size_t)(mrow >> 7) * 4096) * 4
                        + SWZ128((uint32_t)((mrow & 127) * 128 + ((f & 31) >> 2) * 16));
                    *(float4*)dst = make_float4(hv[0], hv[1], hv[2], hv[3]);
                }
            }
        }
    }
    __syncthreads();
    if (tid == 0) {
        MBARRIER_INVAL(ctrl + 8);
        #pragma unroll
        for (int s2 = 0; s2 < NSTG; ++s2) MBARRIER_INVAL(ctrl + 16 + 8 * s2);
    }
    if (w == 0) { TCGEN05_RELINQUISH(); TCGEN05_DEALLOC(tmem, 512); }
#endif
}

// GEMM2: Z = x + H @ W3^T. 2 m-blocks x 256 n-cols, K=FF.
__global__ void __launch_bounds__(512, 1)
gemm2_tc_kernel(const float* __restrict__ x)
{
#if TC_OK
    int idx = blockIdx.z;
    int Nt = g_cnt[idx];
    int m0 = blockIdx.y * 256;
    if (m0 >= Nt) return;
    int n0 = blockIdx.x * 256;

    const float* Aimg = g_H   + (size_t)idx * 4194304;
    const float* Bimg = g_W3t + (size_t)idx * 2097152;

    extern __shared__ __align__(1024) char smem[];
    uint32_t sb = smem_u32(smem);
    uint32_t ctrl = sb + NSTG * STGB;

    int tid = threadIdx.x;
    int w = tid >> 5;

    if (w == 0) TCGEN05_ALLOC(ctrl, 512);
    if (tid == 0) {
        MBARRIER_INIT(ctrl + 8, 1);
        #pragma unroll
        for (int s2 = 0; s2 < NSTG; ++s2) MBARRIER_INIT(ctrl + 16 + 8 * s2, 1);
    }
    __syncthreads();
    uint32_t tmem;
    asm volatile("ld.shared.b32 %0, [%1];" : "=r"(tmem) : "r"(ctrl));

    const int NCH = FF / 32;   // 64
    if (tid == 0) {
        auto load_chunk = [&](int st, int ch) {
            uint32_t mb = ctrl + 16 + 8 * st;
            uint32_t base = sb + st * STGB;
            MBARRIER_EXPECT_TX(mb, 65536u);
            bulk_g2s(base, Aimg + (size_t)ch * 65536 + (size_t)(m0 >> 7) * 4096, 32768, mb);
            bulk_g2s(base + 32768, Bimg + (size_t)ch * 32768 + (size_t)(n0 >> 7) * 4096, 32768, mb);
        };
        load_chunk(0, 0);
        load_chunk(1, 1);
        for (int it = 0; it < NCH; ++it) {
            int st = it % NSTG;
            if (it >= 1) MBAR_WAIT(ctrl + 8, (it - 1) & 1);
            if (it + 2 < NCH) load_chunk((it + 2) % NSTG, it + 2);
            MBAR_WAIT(ctrl + 16 + 8 * st, (it / NSTG) & 1);
            uint32_t base = sb + st * STGB;
            #pragma unroll
            for (int m = 0; m < 2; ++m) {
                uint64_t ad = MAKE_SMEM_DESC(base + m * 16384u);
                #pragma unroll
                for (int half = 0; half < 2; ++half) {
                    uint64_t bd = MAKE_SMEM_DESC(base + 32768u + half * 16384u);
                    #pragma unroll
                    for (int k = 0; k < 4; ++k)
                        umma_tf32(tmem + m * 256 + half * 128, ad + 2 * k, bd + 2 * k,
                                  IDESC_TF32_N128, (uint32_t)(it > 0 || k > 0));
                }
            }
            TCGEN05_COMMIT(ctrl + 8);
        }
        MBAR_WAIT(ctrl + 8, (NCH - 1) & 1);
    }
    __syncthreads();
    TCGEN05_FENCE_AFTER();

    int lane = tid & 31;
    int sub = w & 3, grp = w >> 2;
    float* Zb = g_Z + (size_t)idx * TT * DD;
    #pragma unroll
    for (int mblk = 0; mblk < 2; ++mblk) {
        int mrow = m0 + mblk * 128 + sub * 32 + lane;
        bool valid = mrow < Nt;
        int tok = valid ? g_tok[idx * TT + mrow] : 0;
        uint32_t tb = tmem + mblk * 256;
        #pragma unroll
        for (int cc = 0; cc < 4; ++cc) {
            uint32_t d1[16];
            TCGEN05_LD_X16(d1, tb + grp * 64 + cc * 16);
            TCGEN05_WAIT_LD();
            if (valid) {
                const float4* xr = (const float4*)(x + (size_t)tok * DD + n0 + grp * 64 + cc * 16);
                float4* p = (float4*)(Zb + (size_t)mrow * DD + n0 + grp * 64 + cc * 16);
                #pragma unroll
                for (int v = 0; v < 4; ++v) {
                    float4 xv = xr[v];
                    p[v] = make_float4(__uint_as_float(d1[4*v])   + xv.x,
                                       __uint_as_float(d1[4*v+1]) + xv.y,
                                       __uint_as_float(d1[4*v+2]) + xv.z,
                                       __uint_as_float(d1[4*v+3]) + xv.w);
                }
            }
        }
    }
    __syncthreads();
    if (tid == 0) {
        MBARRIER_INVAL(ctrl + 8);
        #pragma unroll
        for (int s2 = 0; s2 < NSTG; ++s2) MBARRIER_INVAL(ctrl + 16 + 8 * s2);
    }
    if (w == 0) { TCGEN05_RELINQUISH(); TCGEN05_DEALLOC(tmem, 512); }
#endif
}

// fused: expert LN + expert combine + cluster LN + gate sum
__global__ void final_kernel(const float* __restrict__ loutg, const float* __restrict__ loutb,
                             const float* __restrict__ clng, const float* __restrict__ clnb,
                             float* __restrict__ out)
{
    int t = blockIdx.x;
    int tid = threadIdx.x;                    // 256
    __shared__ float rbuf[18];
    float o[4] = {};
    #pragma unroll
    for (int sI = 0; sI < 2; sI++) {
        float vcmb[4] = {};
        #pragma unroll
        for (int q = 0; q < 2; q++) {
            int slot = g_islot[t * 4 + sI * 2 + q];
            int pos  = g_ipos [t * 4 + sI * 2 + q];
            float cf = g_icoef[t * 4 + sI * 2 + q];
            const float* y = g_Z + ((size_t)slot * TT + pos) * DD;
            const float* gp = loutg + (size_t)slot * DD;
            const float* bp = loutb + (size_t)slot * DD;
            float v[4], s = 0.f, s2 = 0.f;
            #pragma unroll
            for (int r = 0; r < 4; r++) {
                int d = tid + 256 * r;
                v[r] = y[d]; s += v[r]; s2 += v[r] * v[r];
            }
            float mu, rs;
            block_meanvar_256(s, s2, rbuf, mu, rs);
            #pragma unroll
            for (int r = 0; r < 4; r++) {
                int d = tid + 256 * r;
                vcmb[r] += cf * ((v[r] - mu) * rs * gp[d] + bp[d]);
            }
        }
        float s = 0.f, s2 = 0.f;
        #pragma unroll
        for (int r = 0; r < 4; r++) { s += vcmb[r]; s2 += vcmb[r] * vcmb[r]; }
        float mu, rs;
        block_meanvar_256(s, s2, rbuf, mu, rs);
        int cc = g_sel[t * 2 + sI];
        float gt = g_gate[t * 2 + sI];
        #pragma unroll
        for (int r = 0; r < 4; r++) {
            int d = tid + 256 * r;
            o[r] += gt * ((vcmb[r] - mu) * rs * clng[cc * DD + d] + clnb[cc * DD + d]);
        }
    }
    #pragma unroll
    for (int r = 0; r < 4; r++)
        out[(size_t)t * DD + tid + 256 * r] = o[r];
}

// ---------------- launcher ----------------
extern "C" void kernel_launch(void* const* d_in, const int* in_sizes, int n_in,
                              void* d_out, int out_size)
{
    const float* x     = (const float*)d_in[0];
    const float* W1    = (const float*)d_in[1];
    const float* W2    = (const float*)d_in[2];
    const float* W3    = (const float*)d_in[3];
    const float* ling  = (const float*)d_in[4];
    const float* linb  = (const float*)d_in[5];
    const float* loutg = (const float*)d_in[6];
    const float* loutb = (const float*)d_in[7];
    const float* clng  = (const float*)d_in[8];
    const float* clnb  = (const float*)d_in[9];
    const float* Wrc   = (const float*)d_in[10];
    const float* brc   = (const float*)d_in[11];
    const float* Wre   = (const float*)d_in[12];
    const float* bre   = (const float*)d_in[13];
    float* out = (float*)d_out;

    float* w1t; cudaGetSymbolAddress((void**)&w1t, g_W1t);
    float* w2t; cudaGetSymbolAddress((void**)&w2t, g_W2t);
    float* w3t; cudaGetSymbolAddress((void**)&w3t, g_W3t);

    cudaFuncSetAttribute(gemm1_tc_kernel,
                         cudaFuncAttributeMaxDynamicSharedMemorySize, SMEM_TC);
    cudaFuncSetAttribute(gemm2_tc_kernel,
                         cudaFuncAttributeMaxDynamicSharedMemorySize, SMEM_TC);

    zero_cnt_kernel<<<1, 32>>>();                                           // 1
    pack_kernel<<<dim3(FF/32, DD/32, 16), 256>>>(W1, w1t, DD, FF, 0);       // 2
    pack_kernel<<<dim3(FF/32, DD/32, 8),  256>>>(W2, w2t, DD, FF, 1);       // 3
    routing_kernel<<<TT, 128>>>(x, Wrc, brc, Wre, bre, ling, linb);         // 4

    dim3 g1(FF/128, TT/256, NEXP);
    gemm1_tc_kernel<<<g1, 512, SMEM_TC>>>();                                // 5

    pack_kernel<<<dim3(DD/32, FF/32, 16), 256>>>(W3, w3t, FF, DD, 0);       // 6
    dim3 g2(DD/256, TT/256, NEXP);
    gemm2_tc_kernel<<<g2, 512, SMEM_TC>>>(x);                               // 7

    final_kernel<<<TT, 256>>>(loutg, loutb, clng, clnb, out);               // 8
}